// round 1
// baseline (speedup 1.0000x reference)
#include <cuda_runtime.h>

#define SEQ   1024
#define HID   1024
#define BATCH 4
#define NH    513      // HID/2 + 1 columns carried through both stages
#define NHP   520      // padded row stride for P/Q

// ---------------- static device scratch (no runtime allocation) ----------------
__device__ float g_lutc[1024];
__device__ float g_luts[1024];
__device__ float g_cos[HID * HID];          // cos(2*pi*j*k/1024)
__device__ float g_sin[HID * HID];          // sin(2*pi*j*k/1024)
__device__ float g_P[BATCH * SEQ * NHP];    // X @ C  (cols 0..512)
__device__ float g_Q[BATCH * SEQ * NHP];    // X @ S  (cols 0..512)

// ---------------- table generation ----------------
__global__ void fill_lut() {
    int m = blockIdx.x * blockDim.x + threadIdx.x;   // 0..1023
    float s, c;
    sincospif((float)m * (1.0f / 512.0f), &s, &c);   // angle = 2*pi*m/1024 exactly
    g_lutc[m] = c;
    g_luts[m] = s;
}

__global__ void fill_tables() {
    int idx = blockIdx.x * blockDim.x + threadIdx.x; // 0..1M-1
    int j = idx >> 10;
    int k = idx & 1023;
    int m = (j * k) & 1023;                          // (j*k) mod 1024, exact in int
    g_cos[idx] = g_lutc[m];
    g_sin[idx] = g_luts[m];
}

// ---------------- stage 1: P = X@C[:, :NH], Q = X@S[:, :NH] (fused) ----------------
// X flattened [BATCH*SEQ, HID]. Tile 128(rows) x 64(cols), K-step 16.
// 256 threads, micro-tile 8x4, dual accumulators.
__global__ __launch_bounds__(256)
void stage1(const float* __restrict__ X) {
    __shared__ __align__(16) float Xs[16][128];   // X transposed: Xs[kk][r]
    __shared__ __align__(16) float Cs[16][64];
    __shared__ __align__(16) float Ss[16][64];

    int tid = threadIdx.x;
    int tx = tid & 15;          // 0..15 -> 4 cols each
    int ty = tid >> 4;          // 0..15 -> 8 rows each
    int row0 = blockIdx.y * 128;
    int col0 = blockIdx.x * 64;

    float accP[8][4] = {};
    float accQ[8][4] = {};

    for (int k0 = 0; k0 < HID; k0 += 16) {
        #pragma unroll
        for (int t = tid; t < 128 * 16; t += 256) {
            int r = t >> 4, kk = t & 15;
            Xs[kk][r] = X[(row0 + r) * HID + k0 + kk];
        }
        #pragma unroll
        for (int t = tid; t < 16 * 64; t += 256) {
            int kk = t >> 6, c = t & 63;
            int col = col0 + c;
            float cv = 0.f, sv = 0.f;
            if (col < NH) {
                cv = g_cos[(k0 + kk) * HID + col];
                sv = g_sin[(k0 + kk) * HID + col];
            }
            Cs[kk][c] = cv;
            Ss[kk][c] = sv;
        }
        __syncthreads();

        #pragma unroll
        for (int kk = 0; kk < 16; kk++) {
            float4 a0 = *(const float4*)&Xs[kk][ty * 8];
            float4 a1 = *(const float4*)&Xs[kk][ty * 8 + 4];
            float4 bc = *(const float4*)&Cs[kk][tx * 4];
            float4 bs = *(const float4*)&Ss[kk][tx * 4];
            float a[8]  = {a0.x, a0.y, a0.z, a0.w, a1.x, a1.y, a1.z, a1.w};
            float vc[4] = {bc.x, bc.y, bc.z, bc.w};
            float vs[4] = {bs.x, bs.y, bs.z, bs.w};
            #pragma unroll
            for (int i = 0; i < 8; i++) {
                #pragma unroll
                for (int j = 0; j < 4; j++) {
                    accP[i][j] += a[i] * vc[j];
                    accQ[i][j] += a[i] * vs[j];
                }
            }
        }
        __syncthreads();
    }

    #pragma unroll
    for (int i = 0; i < 8; i++) {
        int r = row0 + ty * 8 + i;
        #pragma unroll
        for (int j = 0; j < 4; j++) {
            int c = col0 + tx * 4 + j;
            if (c < NH) {
                g_P[r * NHP + c] = accP[i][j];
                g_Q[r * NHP + c] = accQ[i][j];
            }
        }
    }
}

// ---------------- stage 2: out[:,k]   = (C@P)[:,k] - (S@Q)[:,k]  (k <= 512)
//                           out[:,D-k] = (C@P)[:,k] + (S@Q)[:,k]  (1 <= k <= 511)
// Per batch. Tile 128(rows n) x 64(cols k), K-step 16.
// 128 threads, micro-tile 8x8, dual accumulators (A and B).
__global__ __launch_bounds__(128)
void stage2(float* __restrict__ out) {
    __shared__ __align__(16) float Ac[16][128];   // cos rows, transposed
    __shared__ __align__(16) float Asin[16][128]; // sin rows, transposed
    __shared__ __align__(16) float Ps[16][64];
    __shared__ __align__(16) float Qs[16][64];

    int tid = threadIdx.x;
    int tx = tid & 7;           // 0..7  -> 8 cols each
    int ty = tid >> 3;          // 0..15 -> 8 rows each
    int col0 = blockIdx.x * 64;
    int row0 = blockIdx.y * 128;
    int b    = blockIdx.z;

    const float* Pb = g_P + b * SEQ * NHP;
    const float* Qb = g_Q + b * SEQ * NHP;

    float accA[8][8] = {};
    float accB[8][8] = {};

    for (int k0 = 0; k0 < SEQ; k0 += 16) {
        #pragma unroll
        for (int t = tid; t < 128 * 16; t += 128) {
            int r = t >> 4, kk = t & 15;
            Ac[kk][r]   = g_cos[(row0 + r) * HID + k0 + kk];
            Asin[kk][r] = g_sin[(row0 + r) * HID + k0 + kk];
        }
        #pragma unroll
        for (int t = tid; t < 16 * 64; t += 128) {
            int kk = t >> 6, c = t & 63;
            int col = col0 + c;
            float pv = 0.f, qv = 0.f;
            if (col < NH) {
                pv = Pb[(k0 + kk) * NHP + col];
                qv = Qb[(k0 + kk) * NHP + col];
            }
            Ps[kk][c] = pv;
            Qs[kk][c] = qv;
        }
        __syncthreads();

        #pragma unroll
        for (int kk = 0; kk < 16; kk++) {
            float4 c0 = *(const float4*)&Ac[kk][ty * 8];
            float4 c1 = *(const float4*)&Ac[kk][ty * 8 + 4];
            float4 s0 = *(const float4*)&Asin[kk][ty * 8];
            float4 s1 = *(const float4*)&Asin[kk][ty * 8 + 4];
            float4 p0 = *(const float4*)&Ps[kk][tx * 8];
            float4 p1 = *(const float4*)&Ps[kk][tx * 8 + 4];
            float4 q0 = *(const float4*)&Qs[kk][tx * 8];
            float4 q1 = *(const float4*)&Qs[kk][tx * 8 + 4];
            float ac[8] = {c0.x, c0.y, c0.z, c0.w, c1.x, c1.y, c1.z, c1.w};
            float as[8] = {s0.x, s0.y, s0.z, s0.w, s1.x, s1.y, s1.z, s1.w};
            float p[8]  = {p0.x, p0.y, p0.z, p0.w, p1.x, p1.y, p1.z, p1.w};
            float q[8]  = {q0.x, q0.y, q0.z, q0.w, q1.x, q1.y, q1.z, q1.w};
            #pragma unroll
            for (int i = 0; i < 8; i++) {
                #pragma unroll
                for (int j = 0; j < 8; j++) {
                    accA[i][j] += ac[i] * p[j];
                    accB[i][j] += as[i] * q[j];
                }
            }
        }
        __syncthreads();
    }

    float* outb = out + b * SEQ * HID;
    #pragma unroll
    for (int i = 0; i < 8; i++) {
        int n = row0 + ty * 8 + i;
        float* orow = outb + n * HID;
        #pragma unroll
        for (int jv = 0; jv < 2; jv++) {
            int c0 = col0 + tx * 8 + jv * 4;
            float d[4], m[4];
            #pragma unroll
            for (int jj = 0; jj < 4; jj++) {
                float A = accA[i][jv * 4 + jj];
                float B = accB[i][jv * 4 + jj];
                d[jj] = A - B;   // direct column c
                m[jj] = A + B;   // mirrored column HID - c
            }
            // direct store (cols 0..512)
            if (c0 + 3 < NH) {
                *(float4*)&orow[c0] = make_float4(d[0], d[1], d[2], d[3]);
            } else {
                #pragma unroll
                for (int jj = 0; jj < 4; jj++)
                    if (c0 + jj < NH) orow[c0 + jj] = d[jj];
            }
            // mirror store (cols 513..1023, from c in [1,511]); scalar (alignment)
            #pragma unroll
            for (int jj = 0; jj < 4; jj++) {
                int c = c0 + jj;
                if (c >= 1 && c < 512) orow[HID - c] = m[jj];
            }
        }
    }
}

// ---------------- launcher ----------------
extern "C" void kernel_launch(void* const* d_in, const int* in_sizes, int n_in,
                              void* d_out, int out_size) {
    const float* X = (const float*)d_in[0];   // [BATCH, SEQ, HID] fp32
    float* out = (float*)d_out;               // [BATCH, SEQ, HID] fp32

    fill_lut<<<4, 256>>>();
    fill_tables<<<4096, 256>>>();
    stage1<<<dim3(9, 32), 256>>>(X);          // 9 col-tiles (576 >= 513), 32 row-tiles
    stage2<<<dim3(9, 8, 4), 128>>>(out);      // 9 col-tiles, 8 row-tiles, 4 batches
}

// round 4
// speedup vs baseline: 3.1985x; 3.1985x over previous
#include <cuda_runtime.h>
#include <cstdint>

#define SEQ   1024
#define HID   1024
#define BATCH 4
#define NROWS (BATCH * SEQ)   // 4096 flattened rows
#define NKC   512             // cols 0..511 through tensor path; col 512 (Nyquist) separate

// ---------------- static device scratch ----------------
__device__ float g_lutc[1024];
__device__ float g_luts[1024];
__device__ float g_cos[HID * HID];   // tf32-rounded cos(2*pi*j*k/1024) (symmetric)
__device__ float g_sin[HID * HID];   // tf32-rounded sin
__device__ float g_Xr[NROWS * HID];  // tf32-rounded input
__device__ float g_P[NROWS * NKC];   // X @ C  cols 0..511, tf32-rounded
__device__ float g_Q[NROWS * NKC];   // X @ S
__device__ float g_p512[NROWS];      // X @ alternating-sign column (exact fp32)

// ---------------- helpers ----------------
__device__ __forceinline__ uint32_t smem_u32(const void* p) {
    return (uint32_t)__cvta_generic_to_shared(p);
}
__device__ __forceinline__ uint32_t f2tf32(float x) {
    uint32_t r; asm("cvt.rna.tf32.f32 %0, %1;" : "=r"(r) : "f"(x)); return r;
}
__device__ __forceinline__ float rnd(float x) { return __uint_as_float(f2tf32(x)); }

__device__ __forceinline__ void cpa(uint32_t s, const void* g) {
    asm volatile("cp.async.cg.shared.global [%0], [%1], 16;" :: "r"(s), "l"(g));
}
#define CP_COMMIT asm volatile("cp.async.commit_group;" ::: "memory")
#define CP_WAIT1  asm volatile("cp.async.wait_group 1;" ::: "memory")
#define CP_WAIT0  asm volatile("cp.async.wait_group 0;" ::: "memory")

// D += A(16x8, row) * B(8x8, col) in tf32, fp32 accum
__device__ __forceinline__ void mma8(float* d, const uint32_t* a, const uint32_t* b) {
    asm volatile(
        "mma.sync.aligned.m16n8k8.row.col.f32.tf32.tf32.f32 "
        "{%0,%1,%2,%3}, {%4,%5,%6,%7}, {%8,%9}, {%0,%1,%2,%3};"
        : "+f"(d[0]), "+f"(d[1]), "+f"(d[2]), "+f"(d[3])
        : "r"(a[0]), "r"(a[1]), "r"(a[2]), "r"(a[3]), "r"(b[0]), "r"(b[1]));
}

// ---------------- table generation ----------------
__global__ void fill_lut() {
    int m = blockIdx.x * blockDim.x + threadIdx.x;
    float s, c;
    sincospif((float)m * (1.0f / 512.0f), &s, &c);
    g_lutc[m] = c;
    g_luts[m] = s;
}
__global__ void fill_tables() {
    int idx = blockIdx.x * blockDim.x + threadIdx.x;
    int j = idx >> 10, k = idx & 1023;
    int m = (j * k) & 1023;
    g_cos[idx] = rnd(g_lutc[m]);
    g_sin[idx] = rnd(g_luts[m]);
}
__global__ void round_x(const float* __restrict__ X) {
    int idx = (blockIdx.x * blockDim.x + threadIdx.x) * 4;
    float4 v = *(const float4*)(X + idx);
    float4 o = { rnd(v.x), rnd(v.y), rnd(v.z), rnd(v.w) };
    *(float4*)(g_Xr + idx) = o;
}

// ---------------- stage 1: P = X@C[:, :512], Q = X@S[:, :512] ----------------
// out[r, n] = sum_k X[r,k] * C[n,k]  (C symmetric, K-major both sides).
// CTA tile 128(M=r) x 64(N=n), 8 warps (4Mx2N), warp tile 32x32, BK=16.
__global__ __launch_bounds__(256)
void stage1() {
    __shared__ float Xs[2][128 * 20];
    __shared__ float Cs[2][64 * 20];
    __shared__ float Ss[2][64 * 20];

    const int tid = threadIdx.x;
    const int lane = tid & 31, wid = tid >> 5;
    const int gr = lane >> 2, tg = lane & 3;
    const int m_base = (wid & 3) * 32, n_base = (wid >> 2) * 32;
    const int row0 = blockIdx.y * 128;
    const int n0   = blockIdx.x * 64;

    float dP[2][4][4] = {};
    float dQ[2][4][4] = {};

    const int cr = tid >> 2, cg = (tid & 3) * 4;

    auto load = [&](int ch, int buf) {
        const int k0 = ch * 16;
        #pragma unroll
        for (int i = 0; i < 2; i++) {
            int t = tid + i * 256;
            int r = t >> 2, sg = (t & 3) * 4;
            cpa(smem_u32(&Xs[buf][r * 20 + sg]),
                g_Xr + (size_t)(row0 + r) * HID + k0 + sg);
        }
        if (cr < 64) {
            cpa(smem_u32(&Cs[buf][cr * 20 + cg]),
                g_cos + (size_t)(n0 + cr) * HID + k0 + cg);
            cpa(smem_u32(&Ss[buf][cr * 20 + cg]),
                g_sin + (size_t)(n0 + cr) * HID + k0 + cg);
        }
    };

    auto compute = [&](int buf) {
        const uint32_t* xs = (const uint32_t*)Xs[buf];
        const uint32_t* cs = (const uint32_t*)Cs[buf];
        const uint32_t* ss = (const uint32_t*)Ss[buf];
        #pragma unroll
        for (int j = 0; j < 2; j++) {
            const int kc = j * 8 + tg;
            uint32_t a[2][4];
            #pragma unroll
            for (int mi = 0; mi < 2; mi++) {
                int r = m_base + mi * 16 + gr;
                a[mi][0] = xs[r * 20 + kc];
                a[mi][1] = xs[(r + 8) * 20 + kc];
                a[mi][2] = xs[r * 20 + kc + 4];
                a[mi][3] = xs[(r + 8) * 20 + kc + 4];
            }
            uint32_t bc[4][2], bs[4][2];
            #pragma unroll
            for (int ni = 0; ni < 4; ni++) {
                int n = n_base + ni * 8 + gr;
                bc[ni][0] = cs[n * 20 + kc];
                bc[ni][1] = cs[n * 20 + kc + 4];
                bs[ni][0] = ss[n * 20 + kc];
                bs[ni][1] = ss[n * 20 + kc + 4];
            }
            #pragma unroll
            for (int mi = 0; mi < 2; mi++)
                #pragma unroll
                for (int ni = 0; ni < 4; ni++) {
                    mma8(dP[mi][ni], a[mi], bc[ni]);
                    mma8(dQ[mi][ni], a[mi], bs[ni]);
                }
        }
    };

    load(0, 0); CP_COMMIT;
    for (int ch = 0; ch < 64; ch++) {
        if (ch < 63) { load(ch + 1, (ch + 1) & 1); CP_COMMIT; CP_WAIT1; }
        else         { CP_WAIT0; }
        __syncthreads();
        compute(ch & 1);
        __syncthreads();
    }

    // epilogue: tf32-round and store P, Q (row-major [4096][512])
    #pragma unroll
    for (int mi = 0; mi < 2; mi++) {
        #pragma unroll
        for (int ni = 0; ni < 4; ni++) {
            int r0 = row0 + m_base + mi * 16 + gr;
            int c  = n0 + n_base + ni * 8 + 2 * tg;
            float2 p0 = { rnd(dP[mi][ni][0]), rnd(dP[mi][ni][1]) };
            float2 p1 = { rnd(dP[mi][ni][2]), rnd(dP[mi][ni][3]) };
            float2 q0 = { rnd(dQ[mi][ni][0]), rnd(dQ[mi][ni][1]) };
            float2 q1 = { rnd(dQ[mi][ni][2]), rnd(dQ[mi][ni][3]) };
            *(float2*)&g_P[(size_t)r0 * NKC + c]       = p0;
            *(float2*)&g_P[(size_t)(r0 + 8) * NKC + c] = p1;
            *(float2*)&g_Q[(size_t)r0 * NKC + c]       = q0;
            *(float2*)&g_Q[(size_t)(r0 + 8) * NKC + c] = q1;
        }
    }
}

// ---------------- stage 2: A = C@P, B = S@Q; out direct = A-B, mirror = A+B ----
// out[n, k] = sum_i C[n,i]*P[i,k] - S[n,i]*Q[i,k].  CTA tile 128(n) x 64(k), BK=16.
#define S2_CS  0
#define S2_SS  (2 * 128 * 20)
#define S2_PS  (4 * 128 * 20)
#define S2_QS  (4 * 128 * 20 + 2 * 16 * 72)
#define S2_SMEM_BYTES ((4 * 128 * 20 + 4 * 16 * 72) * 4)

__global__ __launch_bounds__(256)
void stage2(float* __restrict__ out) {
    extern __shared__ float ds2[];

    const int tid = threadIdx.x;
    const int lane = tid & 31, wid = tid >> 5;
    const int gr = lane >> 2, tg = lane & 3;
    const int m_base = (wid & 3) * 32, n_base = (wid >> 2) * 32;
    const int k0   = blockIdx.x * 64;     // output col tile
    const int row0 = blockIdx.y * 128;    // output row tile (n)
    const int b    = blockIdx.z;

    float dA[2][4][4] = {};
    float dB[2][4][4] = {};

    auto load = [&](int ch, int buf) {
        const int i0 = ch * 16;
        float* cb = ds2 + S2_CS + buf * (128 * 20);
        float* sb = ds2 + S2_SS + buf * (128 * 20);
        float* pb = ds2 + S2_PS + buf * (16 * 72);
        float* qb = ds2 + S2_QS + buf * (16 * 72);
        #pragma unroll
        for (int i = 0; i < 2; i++) {
            int t = tid + i * 256;
            int r = t >> 2, sg = (t & 3) * 4;
            cpa(smem_u32(&cb[r * 20 + sg]),
                g_cos + (size_t)(row0 + r) * HID + i0 + sg);
            cpa(smem_u32(&sb[r * 20 + sg]),
                g_sin + (size_t)(row0 + r) * HID + i0 + sg);
        }
        {
            int r = tid >> 4, sg = (tid & 15) * 4;
            size_t gro = (size_t)(b * SEQ + i0 + r) * NKC + k0 + sg;
            cpa(smem_u32(&pb[r * 72 + sg]), g_P + gro);
            cpa(smem_u32(&qb[r * 72 + sg]), g_Q + gro);
        }
    };

    auto compute = [&](int buf) {
        const uint32_t* cs = (const uint32_t*)(ds2 + S2_CS + buf * (128 * 20));
        const uint32_t* ss = (const uint32_t*)(ds2 + S2_SS + buf * (128 * 20));
        const uint32_t* ps = (const uint32_t*)(ds2 + S2_PS + buf * (16 * 72));
        const uint32_t* qs = (const uint32_t*)(ds2 + S2_QS + buf * (16 * 72));
        #pragma unroll
        for (int j = 0; j < 2; j++) {
            const int kc = j * 8 + tg;
            uint32_t aC[2][4], aS[2][4];
            #pragma unroll
            for (int mi = 0; mi < 2; mi++) {
                int r = m_base + mi * 16 + gr;
                aC[mi][0] = cs[r * 20 + kc];
                aC[mi][1] = cs[(r + 8) * 20 + kc];
                aC[mi][2] = cs[r * 20 + kc + 4];
                aC[mi][3] = cs[(r + 8) * 20 + kc + 4];
                aS[mi][0] = ss[r * 20 + kc];
                aS[mi][1] = ss[(r + 8) * 20 + kc];
                aS[mi][2] = ss[r * 20 + kc + 4];
                aS[mi][3] = ss[(r + 8) * 20 + kc + 4];
            }
            uint32_t bP[4][2], bQ[4][2];
            #pragma unroll
            for (int ni = 0; ni < 4; ni++) {
                int n = n_base + ni * 8 + gr;
                bP[ni][0] = ps[kc * 72 + n];
                bP[ni][1] = ps[(kc + 4) * 72 + n];
                bQ[ni][0] = qs[kc * 72 + n];
                bQ[ni][1] = qs[(kc + 4) * 72 + n];
            }
            #pragma unroll
            for (int mi = 0; mi < 2; mi++)
                #pragma unroll
                for (int ni = 0; ni < 4; ni++) {
                    mma8(dA[mi][ni], aC[mi], bP[ni]);
                    mma8(dB[mi][ni], aS[mi], bQ[ni]);
                }
        }
    };

    load(0, 0); CP_COMMIT;
    for (int ch = 0; ch < 64; ch++) {
        if (ch < 63) { load(ch + 1, (ch + 1) & 1); CP_COMMIT; CP_WAIT1; }
        else         { CP_WAIT0; }
        __syncthreads();
        compute(ch & 1);
        __syncthreads();
    }

    // epilogue: direct cols k (A-B), mirrored cols 1024-k (A+B)
    float* outb = out + (size_t)b * SEQ * HID;
    #pragma unroll
    for (int mi = 0; mi < 2; mi++) {
        #pragma unroll
        for (int ni = 0; ni < 4; ni++) {
            int col = k0 + n_base + ni * 8 + 2 * tg;   // even, 0..510
            #pragma unroll
            for (int h = 0; h < 2; h++) {
                int r = row0 + m_base + mi * 16 + gr + h * 8;
                float A0 = dA[mi][ni][h * 2],     B0 = dB[mi][ni][h * 2];
                float A1 = dA[mi][ni][h * 2 + 1], B1 = dB[mi][ni][h * 2 + 1];
                float* orow = outb + (size_t)r * HID;
                float2 dv = { A0 - B0, A1 - B1 };
                *(float2*)&orow[col] = dv;
                if (col != 0) orow[HID - col] = A0 + B0;
                orow[HID - col - 1] = A1 + B1;
            }
        }
    }
}

// ---------------- Nyquist column (k = 512): exact fp32, Q component is zero ----------------
__global__ void nyq1(const float* __restrict__ X) {
    int wid = threadIdx.x >> 5, lid = threadIdx.x & 31;
    int row = blockIdx.x * 8 + wid;
    const float* xr = X + (size_t)row * HID + lid * 32;
    float acc = 0.f;
    #pragma unroll
    for (int q = 0; q < 8; q++) {
        float4 v = *(const float4*)(xr + q * 4);
        acc += (v.x - v.y) + (v.z - v.w);
    }
    #pragma unroll
    for (int o = 16; o; o >>= 1) acc += __shfl_xor_sync(0xFFFFFFFFu, acc, o);
    if (lid == 0) g_p512[row] = acc;
}
__global__ void nyq2(float* __restrict__ out) {
    int wid = threadIdx.x >> 5, lid = threadIdx.x & 31;
    int id = blockIdx.x * 8 + wid;
    int b = id >> 10, n = id & 1023;
    const float* cr = g_cos + (size_t)n * HID + lid * 32;
    const float* pr = g_p512 + (size_t)b * SEQ + lid * 32;
    float acc = 0.f;
    #pragma unroll
    for (int q = 0; q < 8; q++) {
        float4 c = *(const float4*)(cr + q * 4);
        float4 p = *(const float4*)(pr + q * 4);
        acc += c.x * p.x + c.y * p.y + c.z * p.z + c.w * p.w;
    }
    #pragma unroll
    for (int o = 16; o; o >>= 1) acc += __shfl_xor_sync(0xFFFFFFFFu, acc, o);
    if (lid == 0) out[((size_t)b * SEQ + n) * HID + 512] = acc;
}

// ---------------- launcher ----------------
extern "C" void kernel_launch(void* const* d_in, const int* in_sizes, int n_in,
                              void* d_out, int out_size) {
    const float* X = (const float*)d_in[0];
    float* out = (float*)d_out;

    cudaFuncSetAttribute(stage2, cudaFuncAttributeMaxDynamicSharedMemorySize, S2_SMEM_BYTES);

    fill_lut<<<4, 256>>>();
    fill_tables<<<4096, 256>>>();
    round_x<<<4096, 256>>>(X);
    nyq1<<<512, 256>>>(X);
    stage1<<<dim3(8, 32), 256>>>();
    stage2<<<dim3(8, 8, 4), 256, S2_SMEM_BYTES>>>(out);
    nyq2<<<512, 256>>>(out);
}

// round 5
// speedup vs baseline: 4.8758x; 1.5244x over previous
#include <cuda_runtime.h>
#include <cstdint>

#define SEQ   1024
#define HID   1024
#define BATCH 4
#define NROWS (BATCH * SEQ)   // 4096 flattened rows
#define NKC   512             // folded K and column count

// ---------------- static device scratch ----------------
__device__ float g_lutc[1024];
__device__ float g_luts[1024];
__device__ float g_cos[HID * HID];    // tf32-rounded cos(2*pi*j*k/1024) (symmetric)
__device__ float g_sin[HID * HID];    // tf32-rounded sin
__device__ float g_Xe[NROWS * NKC];   // even fold of X (tf32)
__device__ float g_Xo[NROWS * NKC];   // odd fold of X (tf32)
__device__ float g_x512[NROWS];       // X[r,512] raw fp32
__device__ float g_P[NROWS * NKC];    // X @ C  cols 0..511 (tf32, incl. correction)
__device__ float g_Q[NROWS * NKC];    // X @ S
__device__ float g_Pe[BATCH * 512 * NKC];  // even fold of P over seq axis (tf32)
__device__ float g_Qo[BATCH * 512 * NKC];  // odd fold of Q
__device__ float g_p512[NROWS];       // X @ alternating column (exact fp32)

// ---------------- helpers ----------------
__device__ __forceinline__ uint32_t smem_u32(const void* p) {
    return (uint32_t)__cvta_generic_to_shared(p);
}
__device__ __forceinline__ uint32_t f2tf32(float x) {
    uint32_t r; asm("cvt.rna.tf32.f32 %0, %1;" : "=r"(r) : "f"(x)); return r;
}
__device__ __forceinline__ float rnd(float x) { return __uint_as_float(f2tf32(x)); }

__device__ __forceinline__ void cpa(uint32_t s, const void* g) {
    asm volatile("cp.async.cg.shared.global [%0], [%1], 16;" :: "r"(s), "l"(g));
}
#define CP_COMMIT asm volatile("cp.async.commit_group;" ::: "memory")
#define CP_WAIT1  asm volatile("cp.async.wait_group 1;" ::: "memory")
#define CP_WAIT0  asm volatile("cp.async.wait_group 0;" ::: "memory")

// D += A(16x8, row) * B(8x8, col) in tf32, fp32 accum
__device__ __forceinline__ void mma8(float* d, const uint32_t* a, const uint32_t* b) {
    asm volatile(
        "mma.sync.aligned.m16n8k8.row.col.f32.tf32.tf32.f32 "
        "{%0,%1,%2,%3}, {%4,%5,%6,%7}, {%8,%9}, {%0,%1,%2,%3};"
        : "+f"(d[0]), "+f"(d[1]), "+f"(d[2]), "+f"(d[3])
        : "r"(a[0]), "r"(a[1]), "r"(a[2]), "r"(a[3]), "r"(b[0]), "r"(b[1]));
}

// ---------------- table generation ----------------
__global__ void fill_lut() {
    int m = blockIdx.x * blockDim.x + threadIdx.x;
    float s, c;
    sincospif((float)m * (1.0f / 512.0f), &s, &c);
    g_lutc[m] = c;
    g_luts[m] = s;
}
__global__ void fill_tables() {
    int idx = blockIdx.x * blockDim.x + threadIdx.x;
    int j = idx >> 10, k = idx & 1023;
    int m = (j * k) & 1023;
    g_cos[idx] = rnd(g_lutc[m]);
    g_sin[idx] = rnd(g_luts[m]);
}

// ---------------- fold X: Xe/Xo[r,k] = X[r,k] +/- X[r,1024-k], k=0..511 ----------------
__global__ void foldX(const float* __restrict__ X) {
    int gid = blockIdx.x * blockDim.x + threadIdx.x;   // 4096*128 groups
    int r = gid >> 7;
    int kg = (gid & 127) * 4;
    const float* Xrow = X + (size_t)r * HID;
    float4 fx = *(const float4*)(Xrow + kg);
    float fv[4] = { fx.x, fx.y, fx.z, fx.w };
    float e[4], o[4];
    #pragma unroll
    for (int j = 0; j < 4; j++) {
        int k = kg + j;
        if (k == 0) { e[0] = rnd(fv[0]); o[0] = 0.f; }
        else {
            float m = Xrow[1024 - k];
            e[j] = rnd(fv[j] + m);
            o[j] = rnd(fv[j] - m);
        }
    }
    *(float4*)(g_Xe + (size_t)r * NKC + kg) = make_float4(e[0], e[1], e[2], e[3]);
    *(float4*)(g_Xo + (size_t)r * NKC + kg) = make_float4(o[0], o[1], o[2], o[3]);
    if (kg == 0) g_x512[r] = Xrow[512];
}

// ---------------- fold P/Q over seq axis (per batch) ----------------
__global__ void foldPQ() {
    int gid = blockIdx.x * blockDim.x + threadIdx.x;   // 4*512*128 groups
    int b = gid >> 16;
    int rem = gid & 65535;
    int i = rem >> 7;
    int kg = (rem & 127) * 4;
    size_t dst = ((size_t)b * 512 + i) * NKC + kg;
    if (i == 0) {
        float4 p = *(const float4*)(g_P + ((size_t)b * 1024) * NKC + kg);
        *(float4*)(g_Pe + dst) = p;   // already tf32-rounded
        *(float4*)(g_Qo + dst) = make_float4(0.f, 0.f, 0.f, 0.f);
    } else {
        float4 p0 = *(const float4*)(g_P + ((size_t)b * 1024 + i) * NKC + kg);
        float4 p1 = *(const float4*)(g_P + ((size_t)b * 1024 + 1024 - i) * NKC + kg);
        float4 q0 = *(const float4*)(g_Q + ((size_t)b * 1024 + i) * NKC + kg);
        float4 q1 = *(const float4*)(g_Q + ((size_t)b * 1024 + 1024 - i) * NKC + kg);
        *(float4*)(g_Pe + dst) = make_float4(rnd(p0.x + p1.x), rnd(p0.y + p1.y),
                                             rnd(p0.z + p1.z), rnd(p0.w + p1.w));
        *(float4*)(g_Qo + dst) = make_float4(rnd(q0.x - q1.x), rnd(q0.y - q1.y),
                                             rnd(q0.z - q1.z), rnd(q0.w - q1.w));
    }
}

// ---------------- stage 1: P = Xe@C[:, :512] + corr, Q = Xo@S[:, :512] ----------------
// CTA tile 128(M=r) x 64(N=n), 8 warps (4Mx2N), warp tile 32x32, BK=16, K=512.
#define S1_XE 0
#define S1_XO (2 * 128 * 20)
#define S1_CS (4 * 128 * 20)
#define S1_SS (4 * 128 * 20 + 2 * 64 * 20)
#define S1_SMEM_BYTES ((4 * 128 * 20 + 4 * 64 * 20) * 4)

__global__ __launch_bounds__(256)
void stage1() {
    extern __shared__ float ds1[];

    const int tid = threadIdx.x;
    const int lane = tid & 31, wid = tid >> 5;
    const int gr = lane >> 2, tg = lane & 3;
    const int m_base = (wid & 3) * 32, n_base = (wid >> 2) * 32;
    const int row0 = blockIdx.y * 128;
    const int n0   = blockIdx.x * 64;

    float dP[2][4][4] = {};
    float dQ[2][4][4] = {};

    auto load = [&](int ch, int buf) {
        const int k0 = ch * 16;
        float* xe = ds1 + S1_XE + buf * (128 * 20);
        float* xo = ds1 + S1_XO + buf * (128 * 20);
        float* cb = ds1 + S1_CS + buf * (64 * 20);
        float* sb = ds1 + S1_SS + buf * (64 * 20);
        #pragma unroll
        for (int i = 0; i < 2; i++) {
            int t = tid + i * 256;
            int r = t >> 2, sg = (t & 3) * 4;
            size_t gsrc = (size_t)(row0 + r) * NKC + k0 + sg;
            cpa(smem_u32(&xe[r * 20 + sg]), g_Xe + gsrc);
            cpa(smem_u32(&xo[r * 20 + sg]), g_Xo + gsrc);
        }
        {
            int cr = tid >> 2, cg = (tid & 3) * 4;
            cpa(smem_u32(&cb[cr * 20 + cg]),
                g_cos + (size_t)(n0 + cr) * HID + k0 + cg);
            cpa(smem_u32(&sb[cr * 20 + cg]),
                g_sin + (size_t)(n0 + cr) * HID + k0 + cg);
        }
    };

    auto compute = [&](int buf) {
        const uint32_t* xe = (const uint32_t*)(ds1 + S1_XE + buf * (128 * 20));
        const uint32_t* xo = (const uint32_t*)(ds1 + S1_XO + buf * (128 * 20));
        const uint32_t* cs = (const uint32_t*)(ds1 + S1_CS + buf * (64 * 20));
        const uint32_t* ss = (const uint32_t*)(ds1 + S1_SS + buf * (64 * 20));
        #pragma unroll
        for (int j = 0; j < 2; j++) {
            const int kc = j * 8 + tg;
            uint32_t aE[2][4], aO[2][4];
            #pragma unroll
            for (int mi = 0; mi < 2; mi++) {
                int r = m_base + mi * 16 + gr;
                aE[mi][0] = xe[r * 20 + kc];
                aE[mi][1] = xe[(r + 8) * 20 + kc];
                aE[mi][2] = xe[r * 20 + kc + 4];
                aE[mi][3] = xe[(r + 8) * 20 + kc + 4];
                aO[mi][0] = xo[r * 20 + kc];
                aO[mi][1] = xo[(r + 8) * 20 + kc];
                aO[mi][2] = xo[r * 20 + kc + 4];
                aO[mi][3] = xo[(r + 8) * 20 + kc + 4];
            }
            uint32_t bc[4][2], bs[4][2];
            #pragma unroll
            for (int ni = 0; ni < 4; ni++) {
                int n = n_base + ni * 8 + gr;
                bc[ni][0] = cs[n * 20 + kc];
                bc[ni][1] = cs[n * 20 + kc + 4];
                bs[ni][0] = ss[n * 20 + kc];
                bs[ni][1] = ss[n * 20 + kc + 4];
            }
            #pragma unroll
            for (int mi = 0; mi < 2; mi++)
                #pragma unroll
                for (int ni = 0; ni < 4; ni++) {
                    mma8(dP[mi][ni], aE[mi], bc[ni]);
                    mma8(dQ[mi][ni], aO[mi], bs[ni]);
                }
        }
    };

    load(0, 0); CP_COMMIT;
    for (int ch = 0; ch < 32; ch++) {
        if (ch < 31) { load(ch + 1, (ch + 1) & 1); CP_COMMIT; CP_WAIT1; }
        else         { CP_WAIT0; }
        __syncthreads();
        compute(ch & 1);
        __syncthreads();
    }

    // epilogue: P += (-1)^n * X[r,512]; tf32-round and store
    #pragma unroll
    for (int mi = 0; mi < 2; mi++) {
        int r0 = row0 + m_base + mi * 16 + gr;
        float xa = g_x512[r0];
        float xb = g_x512[r0 + 8];
        #pragma unroll
        for (int ni = 0; ni < 4; ni++) {
            int c = n0 + n_base + ni * 8 + 2 * tg;   // even
            float2 p0 = { rnd(dP[mi][ni][0] + xa), rnd(dP[mi][ni][1] - xa) };
            float2 p1 = { rnd(dP[mi][ni][2] + xb), rnd(dP[mi][ni][3] - xb) };
            float2 q0 = { rnd(dQ[mi][ni][0]), rnd(dQ[mi][ni][1]) };
            float2 q1 = { rnd(dQ[mi][ni][2]), rnd(dQ[mi][ni][3]) };
            *(float2*)&g_P[(size_t)r0 * NKC + c]       = p0;
            *(float2*)&g_P[(size_t)(r0 + 8) * NKC + c] = p1;
            *(float2*)&g_Q[(size_t)r0 * NKC + c]       = q0;
            *(float2*)&g_Q[(size_t)(r0 + 8) * NKC + c] = q1;
        }
    }
}

// ---------------- stage 2: A = C@Pe + corr, B = S@Qo; 4-quadrant scatter ----------------
// CTA tile 128(n) x 64(k), BK=16, K=512, n in 0..511 only.
#define S2_CS  0
#define S2_SS  (2 * 128 * 20)
#define S2_PS  (4 * 128 * 20)
#define S2_QS  (4 * 128 * 20 + 2 * 16 * 72)
#define S2_SMEM_BYTES ((4 * 128 * 20 + 4 * 16 * 72) * 4)

__global__ __launch_bounds__(256)
void stage2(float* __restrict__ out) {
    extern __shared__ float ds2[];

    const int tid = threadIdx.x;
    const int lane = tid & 31, wid = tid >> 5;
    const int gr = lane >> 2, tg = lane & 3;
    const int m_base = (wid & 3) * 32, n_base = (wid >> 2) * 32;
    const int k0   = blockIdx.x * 64;     // output col tile (0..448)
    const int row0 = blockIdx.y * 128;    // output row tile (0..384)
    const int b    = blockIdx.z;

    float dA[2][4][4] = {};
    float dB[2][4][4] = {};

    auto load = [&](int ch, int buf) {
        const int i0 = ch * 16;
        float* cb = ds2 + S2_CS + buf * (128 * 20);
        float* sb = ds2 + S2_SS + buf * (128 * 20);
        float* pb = ds2 + S2_PS + buf * (16 * 72);
        float* qb = ds2 + S2_QS + buf * (16 * 72);
        #pragma unroll
        for (int i = 0; i < 2; i++) {
            int t = tid + i * 256;
            int r = t >> 2, sg = (t & 3) * 4;
            cpa(smem_u32(&cb[r * 20 + sg]),
                g_cos + (size_t)(row0 + r) * HID + i0 + sg);
            cpa(smem_u32(&sb[r * 20 + sg]),
                g_sin + (size_t)(row0 + r) * HID + i0 + sg);
        }
        {
            int r = tid >> 4, sg = (tid & 15) * 4;
            size_t gro = ((size_t)b * 512 + i0 + r) * NKC + k0 + sg;
            cpa(smem_u32(&pb[r * 72 + sg]), g_Pe + gro);
            cpa(smem_u32(&qb[r * 72 + sg]), g_Qo + gro);
        }
    };

    auto compute = [&](int buf) {
        const uint32_t* cs = (const uint32_t*)(ds2 + S2_CS + buf * (128 * 20));
        const uint32_t* ss = (const uint32_t*)(ds2 + S2_SS + buf * (128 * 20));
        const uint32_t* ps = (const uint32_t*)(ds2 + S2_PS + buf * (16 * 72));
        const uint32_t* qs = (const uint32_t*)(ds2 + S2_QS + buf * (16 * 72));
        #pragma unroll
        for (int j = 0; j < 2; j++) {
            const int kc = j * 8 + tg;
            uint32_t aC[2][4], aS[2][4];
            #pragma unroll
            for (int mi = 0; mi < 2; mi++) {
                int r = m_base + mi * 16 + gr;
                aC[mi][0] = cs[r * 20 + kc];
                aC[mi][1] = cs[(r + 8) * 20 + kc];
                aC[mi][2] = cs[r * 20 + kc + 4];
                aC[mi][3] = cs[(r + 8) * 20 + kc + 4];
                aS[mi][0] = ss[r * 20 + kc];
                aS[mi][1] = ss[(r + 8) * 20 + kc];
                aS[mi][2] = ss[r * 20 + kc + 4];
                aS[mi][3] = ss[(r + 8) * 20 + kc + 4];
            }
            uint32_t bP[4][2], bQ[4][2];
            #pragma unroll
            for (int ni = 0; ni < 4; ni++) {
                int n = n_base + ni * 8 + gr;
                bP[ni][0] = ps[kc * 72 + n];
                bP[ni][1] = ps[(kc + 4) * 72 + n];
                bQ[ni][0] = qs[kc * 72 + n];
                bQ[ni][1] = qs[(kc + 4) * 72 + n];
            }
            #pragma unroll
            for (int mi = 0; mi < 2; mi++)
                #pragma unroll
                for (int ni = 0; ni < 4; ni++) {
                    mma8(dA[mi][ni], aC[mi], bP[ni]);
                    mma8(dB[mi][ni], aS[mi], bQ[ni]);
                }
        }
    };

    load(0, 0); CP_COMMIT;
    for (int ch = 0; ch < 32; ch++) {
        if (ch < 31) { load(ch + 1, (ch + 1) & 1); CP_COMMIT; CP_WAIT1; }
        else         { CP_WAIT0; }
        __syncthreads();
        compute(ch & 1);
        __syncthreads();
    }

    // load P[b, row 512, k0..k0+63] into smem for the rank-1 correction
    float* sc = ds2;
    if (tid < 64) sc[tid] = g_P[((size_t)b * 1024 + 512) * NKC + k0 + tid];
    __syncthreads();

    const float sgn = (gr & 1) ? -1.f : 1.f;   // (-1)^n, n parity = gr parity
    float* outb = out + (size_t)b * SEQ * HID;
    #pragma unroll
    for (int mi = 0; mi < 2; mi++) {
        #pragma unroll
        for (int ni = 0; ni < 4; ni++) {
            int lc = n_base + ni * 8 + 2 * tg;   // local col, even
            int col = k0 + lc;
            float c0corr = sgn * sc[lc];
            float c1corr = sgn * sc[lc + 1];
            #pragma unroll
            for (int h = 0; h < 2; h++) {
                int n = row0 + m_base + mi * 16 + gr + h * 8;   // 0..511
                float A0 = dA[mi][ni][h * 2]     + c0corr;
                float A1 = dA[mi][ni][h * 2 + 1] + c1corr;
                float B0 = dB[mi][ni][h * 2];
                float B1 = dB[mi][ni][h * 2 + 1];
                float d0 = A0 - B0, d1 = A1 - B1;
                float s0 = A0 + B0, s1 = A1 + B1;
                float* orow = outb + (size_t)n * HID;
                *(float2*)&orow[col] = make_float2(d0, d1);
                if (col != 0) orow[HID - col] = s0;
                orow[HID - col - 1] = s1;
                if (n != 0) {
                    float* mrow = outb + (size_t)(HID - n) * HID;
                    *(float2*)&mrow[col] = make_float2(s0, s1);
                    if (col != 0) mrow[HID - col] = d0;
                    mrow[HID - col - 1] = d1;
                }
            }
        }
    }
}

// ---------------- row 512: out[b,512,k] = sum_i (-1)^i P[b,i,k] ----------------
__global__ void gemv512(float* __restrict__ out) {
    __shared__ float red[256];
    const int tid = threadIdx.x;
    const int kk = tid & 63, seg = tid >> 6;
    const int k0 = blockIdx.x * 64;
    const int b  = blockIdx.y;
    float acc = 0.f;
    for (int i = seg; i < 1024; i += 4)
        acc += g_P[((size_t)b * 1024 + i) * NKC + k0 + kk];
    red[seg * 64 + kk] = acc;
    __syncthreads();
    if (tid < 64) {
        float v = red[kk] - red[64 + kk] + red[128 + kk] - red[192 + kk];
        int k = k0 + kk;
        float* orow = out + ((size_t)b * SEQ + 512) * HID;
        orow[k] = v;
        if (k != 0) orow[HID - k] = v;
    }
}

// ---------------- Nyquist column (k = 512): exact fp32 ----------------
__global__ void nyq1(const float* __restrict__ X) {
    int wid = threadIdx.x >> 5, lid = threadIdx.x & 31;
    int row = blockIdx.x * 8 + wid;
    const float* xr = X + (size_t)row * HID + lid * 32;
    float acc = 0.f;
    #pragma unroll
    for (int q = 0; q < 8; q++) {
        float4 v = *(const float4*)(xr + q * 4);
        acc += (v.x - v.y) + (v.z - v.w);
    }
    #pragma unroll
    for (int o = 16; o; o >>= 1) acc += __shfl_xor_sync(0xFFFFFFFFu, acc, o);
    if (lid == 0) g_p512[row] = acc;
}
__global__ void nyq2(float* __restrict__ out) {
    int wid = threadIdx.x >> 5, lid = threadIdx.x & 31;
    int id = blockIdx.x * 8 + wid;
    int b = id >> 10, n = id & 1023;
    const float* cr = g_cos + (size_t)n * HID + lid * 32;
    const float* pr = g_p512 + (size_t)b * SEQ + lid * 32;
    float acc = 0.f;
    #pragma unroll
    for (int q = 0; q < 8; q++) {
        float4 c = *(const float4*)(cr + q * 4);
        float4 p = *(const float4*)(pr + q * 4);
        acc += c.x * p.x + c.y * p.y + c.z * p.z + c.w * p.w;
    }
    #pragma unroll
    for (int o = 16; o; o >>= 1) acc += __shfl_xor_sync(0xFFFFFFFFu, acc, o);
    if (lid == 0) out[((size_t)b * SEQ + n) * HID + 512] = acc;
}

// ---------------- launcher ----------------
extern "C" void kernel_launch(void* const* d_in, const int* in_sizes, int n_in,
                              void* d_out, int out_size) {
    const float* X = (const float*)d_in[0];
    float* out = (float*)d_out;

    cudaFuncSetAttribute(stage1, cudaFuncAttributeMaxDynamicSharedMemorySize, S1_SMEM_BYTES);
    cudaFuncSetAttribute(stage2, cudaFuncAttributeMaxDynamicSharedMemorySize, S2_SMEM_BYTES);

    fill_lut<<<4, 256>>>();
    fill_tables<<<4096, 256>>>();
    foldX<<<2048, 256>>>(X);
    nyq1<<<512, 256>>>(X);
    stage1<<<dim3(8, 32), 256, S1_SMEM_BYTES>>>();
    foldPQ<<<1024, 256>>>();
    gemv512<<<dim3(8, 4), 256>>>(out);
    stage2<<<dim3(8, 4, 4), 256, S2_SMEM_BYTES>>>(out);
    nyq2<<<512, 256>>>(out);
}

// round 6
// speedup vs baseline: 5.8687x; 1.2036x over previous
#include <cuda_runtime.h>
#include <cstdint>

#define SEQ   1024
#define HID   1024
#define BATCH 4
#define NROWS (BATCH * SEQ)   // 4096 flattened rows
#define NKC   512             // folded K and column count

// ---------------- static device scratch ----------------
__device__ float g_lutc[1024];
__device__ float g_luts[1024];
__device__ float g_cos[HID * HID];    // tf32-rounded cos(2*pi*j*k/1024) (symmetric)
__device__ float g_sin[HID * HID];    // tf32-rounded sin
__device__ float g_Xe[NROWS * NKC];   // even fold of X (tf32)
__device__ float g_Xo[NROWS * NKC];   // odd fold of X (tf32)
__device__ float g_x512[NROWS];       // X[r,512] raw fp32
__device__ float g_P[NROWS * NKC];    // X @ C  cols 0..511 (tf32, incl. correction)
__device__ float g_Q[NROWS * NKC];    // X @ S
__device__ float g_Pe[BATCH * 512 * NKC];  // even fold of P over seq axis (tf32)
__device__ float g_Qo[BATCH * 512 * NKC];  // odd fold of Q
__device__ float g_p512[NROWS];       // X @ alternating column (exact fp32)

// ---------------- helpers ----------------
__device__ __forceinline__ uint32_t smem_u32(const void* p) {
    return (uint32_t)__cvta_generic_to_shared(p);
}
__device__ __forceinline__ uint32_t f2tf32(float x) {
    uint32_t r; asm("cvt.rna.tf32.f32 %0, %1;" : "=r"(r) : "f"(x)); return r;
}
__device__ __forceinline__ float rnd(float x) { return __uint_as_float(f2tf32(x)); }

__device__ __forceinline__ void cpa(uint32_t s, const void* g) {
    asm volatile("cp.async.cg.shared.global [%0], [%1], 16;" :: "r"(s), "l"(g));
}
#define CP_COMMIT asm volatile("cp.async.commit_group;" ::: "memory")
#define CP_WAIT1  asm volatile("cp.async.wait_group 1;" ::: "memory")

// D += A(16x8, row) * B(8x8, col) in tf32, fp32 accum
__device__ __forceinline__ void mma8(float* d, const uint32_t* a, const uint32_t* b) {
    asm volatile(
        "mma.sync.aligned.m16n8k8.row.col.f32.tf32.tf32.f32 "
        "{%0,%1,%2,%3}, {%4,%5,%6,%7}, {%8,%9}, {%0,%1,%2,%3};"
        : "+f"(d[0]), "+f"(d[1]), "+f"(d[2]), "+f"(d[3])
        : "r"(a[0]), "r"(a[1]), "r"(a[2]), "r"(a[3]), "r"(b[0]), "r"(b[1]));
}

// ---------------- table generation ----------------
__global__ void fill_lut() {
    int m = blockIdx.x * blockDim.x + threadIdx.x;
    float s, c;
    sincospif((float)m * (1.0f / 512.0f), &s, &c);
    g_lutc[m] = c;
    g_luts[m] = s;
}
__global__ void fill_tables() {
    int idx = blockIdx.x * blockDim.x + threadIdx.x;
    int j = idx >> 10, k = idx & 1023;
    int m = (j * k) & 1023;
    g_cos[idx] = rnd(g_lutc[m]);
    g_sin[idx] = rnd(g_luts[m]);
}

// ---------------- fold X + fused Nyquist row-sum ----------------
// Xe/Xo[r,k] = X[r,k] +/- X[r,1024-k], k=0..511 (tf32-rounded);
// p512[r] = sum_k (-1)^k X[r,k] (exact fp32, from unrounded fold terms).
__global__ __launch_bounds__(256)
void foldX(const float* __restrict__ X) {
    __shared__ float s_red[8];
    const int tid = threadIdx.x;
    const int rloc = tid >> 7;              // 0..1 (two rows per block)
    const int l128 = tid & 127;
    const int r = blockIdx.x * 2 + rloc;
    const int kg = l128 * 4;
    const float* Xrow = X + (size_t)r * HID;

    float4 fx = *(const float4*)(Xrow + kg);
    float fv[4] = { fx.x, fx.y, fx.z, fx.w };
    float e[4], o[4];
    float part = 0.f;
    #pragma unroll
    for (int j = 0; j < 4; j++) {
        int k = kg + j;
        if (k == 0) {
            e[0] = rnd(fv[0]); o[0] = 0.f;
            part += fv[0];
        } else {
            float m = Xrow[1024 - k];
            float sum = fv[j] + m, dif = fv[j] - m;
            e[j] = rnd(sum);
            o[j] = rnd(dif);
            part += (k & 1) ? -sum : sum;
        }
    }
    if (kg == 0) {
        float x5 = Xrow[512];
        g_x512[r] = x5;
        part += x5;
    }
    *(float4*)(g_Xe + (size_t)r * NKC + kg) = make_float4(e[0], e[1], e[2], e[3]);
    *(float4*)(g_Xo + (size_t)r * NKC + kg) = make_float4(o[0], o[1], o[2], o[3]);

    // reduce 'part' over the 128 threads of this row (4 warps each)
    #pragma unroll
    for (int off = 16; off; off >>= 1) part += __shfl_xor_sync(0xFFFFFFFFu, part, off);
    if ((tid & 31) == 0) s_red[tid >> 5] = part;
    __syncthreads();
    if ((tid & 127) == 0) {
        int w0 = rloc * 4;
        g_p512[r] = s_red[w0] + s_red[w0 + 1] + s_red[w0 + 2] + s_red[w0 + 3];
    }
}

// ---------------- fold P/Q over seq axis (per batch) ----------------
__global__ void foldPQ() {
    int gid = blockIdx.x * blockDim.x + threadIdx.x;   // 4*512*128 groups
    int b = gid >> 16;
    int rem = gid & 65535;
    int i = rem >> 7;
    int kg = (rem & 127) * 4;
    size_t dst = ((size_t)b * 512 + i) * NKC + kg;
    if (i == 0) {
        float4 p = *(const float4*)(g_P + ((size_t)b * 1024) * NKC + kg);
        *(float4*)(g_Pe + dst) = p;   // already tf32-rounded
        *(float4*)(g_Qo + dst) = make_float4(0.f, 0.f, 0.f, 0.f);
    } else {
        float4 p0 = *(const float4*)(g_P + ((size_t)b * 1024 + i) * NKC + kg);
        float4 p1 = *(const float4*)(g_P + ((size_t)b * 1024 + 1024 - i) * NKC + kg);
        float4 q0 = *(const float4*)(g_Q + ((size_t)b * 1024 + i) * NKC + kg);
        float4 q1 = *(const float4*)(g_Q + ((size_t)b * 1024 + 1024 - i) * NKC + kg);
        *(float4*)(g_Pe + dst) = make_float4(rnd(p0.x + p1.x), rnd(p0.y + p1.y),
                                             rnd(p0.z + p1.z), rnd(p0.w + p1.w));
        *(float4*)(g_Qo + dst) = make_float4(rnd(q0.x - q1.x), rnd(q0.y - q1.y),
                                             rnd(q0.z - q1.z), rnd(q0.w - q1.w));
    }
}

// ---------------- stage 1: P = Xe@C[:, :512] + corr, Q = Xo@S[:, :512] ----------------
// CTA tile 128(M=r) x 64(N=n), 8 warps (4Mx2N), warp tile 32x32, BK=16, K=512.
// 3-stage cp.async pipeline, one barrier per chunk.
#define S1_BUF_F (2 * 128 * 20 + 2 * 64 * 20)   // floats per stage buffer
#define S1_XE 0
#define S1_XO (128 * 20)
#define S1_CS (2 * 128 * 20)
#define S1_SS (2 * 128 * 20 + 64 * 20)
#define S1_SMEM_BYTES (3 * S1_BUF_F * 4)

__global__ __launch_bounds__(256)
void stage1() {
    extern __shared__ float ds1[];

    const int tid = threadIdx.x;
    const int lane = tid & 31, wid = tid >> 5;
    const int gr = lane >> 2, tg = lane & 3;
    const int m_base = (wid & 3) * 32, n_base = (wid >> 2) * 32;
    const int row0 = blockIdx.y * 128;
    const int n0   = blockIdx.x * 64;

    float dP[2][4][4] = {};
    float dQ[2][4][4] = {};

    auto load = [&](int ch, int buf) {
        const int k0 = ch * 16;
        float* base = ds1 + buf * S1_BUF_F;
        float* xe = base + S1_XE;
        float* xo = base + S1_XO;
        float* cb = base + S1_CS;
        float* sb = base + S1_SS;
        #pragma unroll
        for (int i = 0; i < 2; i++) {
            int t = tid + i * 256;
            int r = t >> 2, sg = (t & 3) * 4;
            size_t gsrc = (size_t)(row0 + r) * NKC + k0 + sg;
            cpa(smem_u32(&xe[r * 20 + sg]), g_Xe + gsrc);
            cpa(smem_u32(&xo[r * 20 + sg]), g_Xo + gsrc);
        }
        {
            int cr = tid >> 2, cg = (tid & 3) * 4;
            cpa(smem_u32(&cb[cr * 20 + cg]),
                g_cos + (size_t)(n0 + cr) * HID + k0 + cg);
            cpa(smem_u32(&sb[cr * 20 + cg]),
                g_sin + (size_t)(n0 + cr) * HID + k0 + cg);
        }
    };

    auto compute = [&](int buf) {
        const float* base = ds1 + buf * S1_BUF_F;
        const uint32_t* xe = (const uint32_t*)(base + S1_XE);
        const uint32_t* xo = (const uint32_t*)(base + S1_XO);
        const uint32_t* cs = (const uint32_t*)(base + S1_CS);
        const uint32_t* ss = (const uint32_t*)(base + S1_SS);
        #pragma unroll
        for (int j = 0; j < 2; j++) {
            const int kc = j * 8 + tg;
            uint32_t aE[2][4], aO[2][4];
            #pragma unroll
            for (int mi = 0; mi < 2; mi++) {
                int r = m_base + mi * 16 + gr;
                aE[mi][0] = xe[r * 20 + kc];
                aE[mi][1] = xe[(r + 8) * 20 + kc];
                aE[mi][2] = xe[r * 20 + kc + 4];
                aE[mi][3] = xe[(r + 8) * 20 + kc + 4];
                aO[mi][0] = xo[r * 20 + kc];
                aO[mi][1] = xo[(r + 8) * 20 + kc];
                aO[mi][2] = xo[r * 20 + kc + 4];
                aO[mi][3] = xo[(r + 8) * 20 + kc + 4];
            }
            uint32_t bc[4][2], bs[4][2];
            #pragma unroll
            for (int ni = 0; ni < 4; ni++) {
                int n = n_base + ni * 8 + gr;
                bc[ni][0] = cs[n * 20 + kc];
                bc[ni][1] = cs[n * 20 + kc + 4];
                bs[ni][0] = ss[n * 20 + kc];
                bs[ni][1] = ss[n * 20 + kc + 4];
            }
            #pragma unroll
            for (int mi = 0; mi < 2; mi++)
                #pragma unroll
                for (int ni = 0; ni < 4; ni++) {
                    mma8(dP[mi][ni], aE[mi], bc[ni]);
                    mma8(dQ[mi][ni], aO[mi], bs[ni]);
                }
        }
    };

    load(0, 0); CP_COMMIT;
    load(1, 1); CP_COMMIT;
    #pragma unroll 1
    for (int ch = 0; ch < 32; ch++) {
        CP_WAIT1;
        __syncthreads();
        compute(ch % 3);
        if (ch + 2 < 32) { load(ch + 2, (ch + 2) % 3); CP_COMMIT; }
    }

    // epilogue: P += (-1)^n * X[r,512]; tf32-round and store
    #pragma unroll
    for (int mi = 0; mi < 2; mi++) {
        int r0 = row0 + m_base + mi * 16 + gr;
        float xa = g_x512[r0];
        float xb = g_x512[r0 + 8];
        #pragma unroll
        for (int ni = 0; ni < 4; ni++) {
            int c = n0 + n_base + ni * 8 + 2 * tg;   // even
            float2 p0 = { rnd(dP[mi][ni][0] + xa), rnd(dP[mi][ni][1] - xa) };
            float2 p1 = { rnd(dP[mi][ni][2] + xb), rnd(dP[mi][ni][3] - xb) };
            float2 q0 = { rnd(dQ[mi][ni][0]), rnd(dQ[mi][ni][1]) };
            float2 q1 = { rnd(dQ[mi][ni][2]), rnd(dQ[mi][ni][3]) };
            *(float2*)&g_P[(size_t)r0 * NKC + c]       = p0;
            *(float2*)&g_P[(size_t)(r0 + 8) * NKC + c] = p1;
            *(float2*)&g_Q[(size_t)r0 * NKC + c]       = q0;
            *(float2*)&g_Q[(size_t)(r0 + 8) * NKC + c] = q1;
        }
    }
}

// ---------------- stage 2: A = C@Pe + corr, B = S@Qo; 4-quadrant scatter ----------------
// CTA tile 128(n) x 64(k), BK=16, K=512, n in 0..511 only. 3-stage pipeline.
#define S2_BUF_F (2 * 128 * 20 + 2 * 16 * 72)
#define S2_CS  0
#define S2_SS  (128 * 20)
#define S2_PS  (2 * 128 * 20)
#define S2_QS  (2 * 128 * 20 + 16 * 72)
#define S2_SMEM_BYTES (3 * S2_BUF_F * 4)

__global__ __launch_bounds__(256)
void stage2(float* __restrict__ out) {
    extern __shared__ float ds2[];

    const int tid = threadIdx.x;
    const int lane = tid & 31, wid = tid >> 5;
    const int gr = lane >> 2, tg = lane & 3;
    const int m_base = (wid & 3) * 32, n_base = (wid >> 2) * 32;
    const int k0   = blockIdx.x * 64;     // output col tile (0..448)
    const int row0 = blockIdx.y * 128;    // output row tile (0..384)
    const int b    = blockIdx.z;

    float dA[2][4][4] = {};
    float dB[2][4][4] = {};

    auto load = [&](int ch, int buf) {
        const int i0 = ch * 16;
        float* base = ds2 + buf * S2_BUF_F;
        float* cb = base + S2_CS;
        float* sb = base + S2_SS;
        float* pb = base + S2_PS;
        float* qb = base + S2_QS;
        #pragma unroll
        for (int i = 0; i < 2; i++) {
            int t = tid + i * 256;
            int r = t >> 2, sg = (t & 3) * 4;
            cpa(smem_u32(&cb[r * 20 + sg]),
                g_cos + (size_t)(row0 + r) * HID + i0 + sg);
            cpa(smem_u32(&sb[r * 20 + sg]),
                g_sin + (size_t)(row0 + r) * HID + i0 + sg);
        }
        {
            int r = tid >> 4, sg = (tid & 15) * 4;
            size_t gro = ((size_t)b * 512 + i0 + r) * NKC + k0 + sg;
            cpa(smem_u32(&pb[r * 72 + sg]), g_Pe + gro);
            cpa(smem_u32(&qb[r * 72 + sg]), g_Qo + gro);
        }
    };

    auto compute = [&](int buf) {
        const float* base = ds2 + buf * S2_BUF_F;
        const uint32_t* cs = (const uint32_t*)(base + S2_CS);
        const uint32_t* ss = (const uint32_t*)(base + S2_SS);
        const uint32_t* ps = (const uint32_t*)(base + S2_PS);
        const uint32_t* qs = (const uint32_t*)(base + S2_QS);
        #pragma unroll
        for (int j = 0; j < 2; j++) {
            const int kc = j * 8 + tg;
            uint32_t aC[2][4], aS[2][4];
            #pragma unroll
            for (int mi = 0; mi < 2; mi++) {
                int r = m_base + mi * 16 + gr;
                aC[mi][0] = cs[r * 20 + kc];
                aC[mi][1] = cs[(r + 8) * 20 + kc];
                aC[mi][2] = cs[r * 20 + kc + 4];
                aC[mi][3] = cs[(r + 8) * 20 + kc + 4];
                aS[mi][0] = ss[r * 20 + kc];
                aS[mi][1] = ss[(r + 8) * 20 + kc];
                aS[mi][2] = ss[r * 20 + kc + 4];
                aS[mi][3] = ss[(r + 8) * 20 + kc + 4];
            }
            uint32_t bP[4][2], bQ[4][2];
            #pragma unroll
            for (int ni = 0; ni < 4; ni++) {
                int n = n_base + ni * 8 + gr;
                bP[ni][0] = ps[kc * 72 + n];
                bP[ni][1] = ps[(kc + 4) * 72 + n];
                bQ[ni][0] = qs[kc * 72 + n];
                bQ[ni][1] = qs[(kc + 4) * 72 + n];
            }
            #pragma unroll
            for (int mi = 0; mi < 2; mi++)
                #pragma unroll
                for (int ni = 0; ni < 4; ni++) {
                    mma8(dA[mi][ni], aC[mi], bP[ni]);
                    mma8(dB[mi][ni], aS[mi], bQ[ni]);
                }
        }
    };

    load(0, 0); CP_COMMIT;
    load(1, 1); CP_COMMIT;
    #pragma unroll 1
    for (int ch = 0; ch < 32; ch++) {
        CP_WAIT1;
        __syncthreads();
        compute(ch % 3);
        if (ch + 2 < 32) { load(ch + 2, (ch + 2) % 3); CP_COMMIT; }
    }

    // load P[b, row 512, k0..k0+63] into smem for the rank-1 correction
    __syncthreads();
    float* sc = ds2;
    if (tid < 64) sc[tid] = g_P[((size_t)b * 1024 + 512) * NKC + k0 + tid];
    __syncthreads();

    const float sgn = (gr & 1) ? -1.f : 1.f;   // (-1)^n, n parity = gr parity
    float* outb = out + (size_t)b * SEQ * HID;
    #pragma unroll
    for (int mi = 0; mi < 2; mi++) {
        #pragma unroll
        for (int ni = 0; ni < 4; ni++) {
            int lc = n_base + ni * 8 + 2 * tg;   // local col, even
            int col = k0 + lc;
            float c0corr = sgn * sc[lc];
            float c1corr = sgn * sc[lc + 1];
            #pragma unroll
            for (int h = 0; h < 2; h++) {
                int n = row0 + m_base + mi * 16 + gr + h * 8;   // 0..511
                float A0 = dA[mi][ni][h * 2]     + c0corr;
                float A1 = dA[mi][ni][h * 2 + 1] + c1corr;
                float B0 = dB[mi][ni][h * 2];
                float B1 = dB[mi][ni][h * 2 + 1];
                float d0 = A0 - B0, d1 = A1 - B1;
                float s0 = A0 + B0, s1 = A1 + B1;
                float* orow = outb + (size_t)n * HID;
                *(float2*)&orow[col] = make_float2(d0, d1);
                if (col != 0) orow[HID - col] = s0;
                orow[HID - col - 1] = s1;
                if (n != 0) {
                    float* mrow = outb + (size_t)(HID - n) * HID;
                    *(float2*)&mrow[col] = make_float2(s0, s1);
                    if (col != 0) mrow[HID - col] = d0;
                    mrow[HID - col - 1] = d1;
                }
            }
        }
    }
}

// ---------------- row 512: out[b,512,k] = sum_i (-1)^i Pe[b,i,k] + P[b,512,k] ----------------
__global__ void gemv512(float* __restrict__ out) {
    __shared__ float red[256];
    const int tid = threadIdx.x;
    const int kk = tid & 63, seg = tid >> 6;
    const int k0 = blockIdx.x * 64;
    const int b  = blockIdx.y;
    float acc = 0.f;
    for (int i = seg; i < 512; i += 4)
        acc += g_Pe[((size_t)b * 512 + i) * NKC + k0 + kk];
    red[seg * 64 + kk] = acc;
    __syncthreads();
    if (tid < 64) {
        int k = k0 + kk;
        float v = red[kk] - red[64 + kk] + red[128 + kk] - red[192 + kk]
                + g_P[((size_t)b * 1024 + 512) * NKC + k];
        float* orow = out + ((size_t)b * SEQ + 512) * HID;
        orow[k] = v;
        if (k != 0) orow[HID - k] = v;
    }
}

// ---------------- Nyquist column (k = 512) from LUT; symmetric in n ----------------
__global__ __launch_bounds__(256)
void nyq2(float* __restrict__ out) {
    __shared__ float lut[1024];
    __shared__ float pv[1024];
    const int b = blockIdx.y;
    for (int t = threadIdx.x; t < 1024; t += 256) {
        lut[t] = g_lutc[t];
        pv[t]  = g_p512[b * 1024 + t];
    }
    __syncthreads();
    const int wid = threadIdx.x >> 5, lid = threadIdx.x & 31;
    const int n = blockIdx.x * 8 + wid;   // 0..519
    if (n <= 512) {
        float acc = 0.f;
        #pragma unroll 8
        for (int t = 0; t < 32; t++) {
            int i = t * 32 + lid;
            acc += lut[(n * i) & 1023] * pv[i];
        }
        #pragma unroll
        for (int o = 16; o; o >>= 1) acc += __shfl_xor_sync(0xFFFFFFFFu, acc, o);
        if (lid == 0) {
            out[((size_t)b * SEQ + n) * HID + 512] = acc;
            if (n >= 1 && n <= 511)
                out[((size_t)b * SEQ + 1024 - n) * HID + 512] = acc;
        }
    }
}

// ---------------- launcher ----------------
extern "C" void kernel_launch(void* const* d_in, const int* in_sizes, int n_in,
                              void* d_out, int out_size) {
    const float* X = (const float*)d_in[0];
    float* out = (float*)d_out;

    cudaFuncSetAttribute(stage1, cudaFuncAttributeMaxDynamicSharedMemorySize, S1_SMEM_BYTES);
    cudaFuncSetAttribute(stage2, cudaFuncAttributeMaxDynamicSharedMemorySize, S2_SMEM_BYTES);

    fill_lut<<<4, 256>>>();
    fill_tables<<<4096, 256>>>();
    foldX<<<2048, 256>>>(X);
    stage1<<<dim3(8, 32), 256, S1_SMEM_BYTES>>>();
    foldPQ<<<1024, 256>>>();
    gemv512<<<dim3(8, 4), 256>>>(out);
    stage2<<<dim3(8, 4, 4), 256, S2_SMEM_BYTES>>>(out);
    nyq2<<<dim3(65, 4), 256>>>(out);
}

// round 7
// speedup vs baseline: 9.7025x; 1.6533x over previous
#include <cuda_runtime.h>
#include <cuda_fp16.h>
#include <cstdint>

#define SEQ   1024
#define HID   1024
#define BATCH 4
#define NROWS (BATCH * SEQ)
#define NKC   512

// ---------------- static device scratch ----------------
__device__ float  g_lutc[1024];
__device__ float  g_luts[1024];
__device__ __half g_cosh[NKC * NKC];       // cos quadrant [n<512][k<512], fp16
__device__ __half g_sinh[NKC * NKC];
__device__ __half g_Xe[NROWS * NKC];       // even fold of X (fp16)
__device__ __half g_Xo[NROWS * NKC];       // odd fold
__device__ float  g_x512[NROWS];           // X[r,512] fp32
__device__ __half g_PT[NKC * NROWS];       // P^T: [k][r]
__device__ __half g_QT[NKC * NROWS];       // Q^T
__device__ __half g_PeT[NKC * BATCH * 512];// Pe^T: [k][b*512+i]
__device__ __half g_QoT[NKC * BATCH * 512];
__device__ float  g_p512[NROWS];           // alternating row-sum of X (fp32)

// ---------------- helpers ----------------
__device__ __forceinline__ uint32_t smem_u32(const void* p) {
    return (uint32_t)__cvta_generic_to_shared(p);
}
__device__ __forceinline__ void cpa(uint32_t s, const void* g) {
    asm volatile("cp.async.cg.shared.global [%0], [%1], 16;" :: "r"(s), "l"(g));
}
#define CP_COMMIT asm volatile("cp.async.commit_group;" ::: "memory")
#define CP_WAIT1  asm volatile("cp.async.wait_group 1;" ::: "memory")

// D += A(16x16 f16, row) * B(16x8 f16, col), fp32 accum
__device__ __forceinline__ void mma16(float* d, const uint32_t* a, const uint32_t* b) {
    asm volatile(
        "mma.sync.aligned.m16n8k16.row.col.f32.f16.f16.f32 "
        "{%0,%1,%2,%3}, {%4,%5,%6,%7}, {%8,%9}, {%0,%1,%2,%3};"
        : "+f"(d[0]), "+f"(d[1]), "+f"(d[2]), "+f"(d[3])
        : "r"(a[0]), "r"(a[1]), "r"(a[2]), "r"(a[3]), "r"(b[0]), "r"(b[1]));
}

// ---------------- table generation ----------------
__global__ void fill_lut() {
    int m = blockIdx.x * blockDim.x + threadIdx.x;
    float s, c;
    sincospif((float)m * (1.0f / 512.0f), &s, &c);
    g_lutc[m] = c;
    g_luts[m] = s;
}
__global__ void fill_tables_h() {
    int idx = blockIdx.x * blockDim.x + threadIdx.x;   // 512*512
    int j = idx >> 9, k = idx & 511;
    int m = (j * k) & 1023;
    g_cosh[idx] = __float2half_rn(g_lutc[m]);
    g_sinh[idx] = __float2half_rn(g_luts[m]);
}

// ---------------- fold X (fp16 out) + fused Nyquist row-sum ----------------
__global__ __launch_bounds__(256)
void foldX(const float* __restrict__ X) {
    __shared__ float s_red[8];
    const int tid = threadIdx.x;
    const int rloc = tid >> 7;
    const int l128 = tid & 127;
    const int r = blockIdx.x * 2 + rloc;
    const int kg = l128 * 4;
    const float* Xrow = X + (size_t)r * HID;

    float4 fx = *(const float4*)(Xrow + kg);
    float fv[4] = { fx.x, fx.y, fx.z, fx.w };
    float e[4], o[4];
    float part = 0.f;
    #pragma unroll
    for (int j = 0; j < 4; j++) {
        int k = kg + j;
        if (k == 0) {
            e[0] = fv[0]; o[0] = 0.f;
            part += fv[0];
        } else {
            float m = Xrow[1024 - k];
            float sum = fv[j] + m, dif = fv[j] - m;
            e[j] = sum;
            o[j] = dif;
            part += (k & 1) ? -sum : sum;
        }
    }
    if (kg == 0) {
        float x5 = Xrow[512];
        g_x512[r] = x5;
        part += x5;
    }
    size_t dst = (size_t)r * NKC + kg;
    *(half2*)(g_Xe + dst)     = __floats2half2_rn(e[0], e[1]);
    *(half2*)(g_Xe + dst + 2) = __floats2half2_rn(e[2], e[3]);
    *(half2*)(g_Xo + dst)     = __floats2half2_rn(o[0], o[1]);
    *(half2*)(g_Xo + dst + 2) = __floats2half2_rn(o[2], o[3]);

    #pragma unroll
    for (int off = 16; off; off >>= 1) part += __shfl_xor_sync(0xFFFFFFFFu, part, off);
    if ((tid & 31) == 0) s_red[tid >> 5] = part;
    __syncthreads();
    if ((tid & 127) == 0) {
        int w0 = rloc * 4;
        g_p512[r] = s_red[w0] + s_red[w0 + 1] + s_red[w0 + 2] + s_red[w0 + 3];
    }
}

// ---------------- stage 1: P^T/Q^T = (Xe@C)^T, (Xo@S)^T, fp16 mma ----------------
// CTA 128(M=r) x 64(N=n), 8 warps 4Mx2N, warp 32x32, BK=32 (2 k16 steps), 16 chunks.
// 3-stage pipeline, 1 barrier/chunk. smem rows: 16 data u32 + 4 pad = stride 20.
#define S_BUF 7680            // u32 per pipeline buffer
#define O_XE  0
#define O_XO  2560
#define O_CB  5120
#define O_SB  6400
#define SMEM_BYTES (3 * S_BUF * 4)
#define TSTR  136             // transpose smem stride (halves)

__global__ __launch_bounds__(256)
void stage1() {
    extern __shared__ uint32_t dsu[];

    const int tid = threadIdx.x;
    const int lane = tid & 31, wid = tid >> 5;
    const int gr = lane >> 2, tg = lane & 3;
    const int m_base = (wid & 3) * 32, n_base = (wid >> 2) * 32;
    const int row0 = blockIdx.y * 128;
    const int n0   = blockIdx.x * 64;

    float dP[2][4][4] = {};
    float dQ[2][4][4] = {};

    auto load = [&](int ch, int buf) {
        const int k0 = ch * 32;   // halves
        uint32_t* base = dsu + buf * S_BUF;
        #pragma unroll
        for (int i = 0; i < 2; i++) {
            int t = tid + i * 256;
            int r = t >> 2, c = t & 3;
            uint32_t off = r * 20 + c * 4;
            size_t gsrc = (size_t)(row0 + r) * NKC + k0 + c * 8;
            cpa(smem_u32(base + O_XE + off), g_Xe + gsrc);
            cpa(smem_u32(base + O_XO + off), g_Xo + gsrc);
        }
        {
            int r = tid >> 2, c = tid & 3;
            uint32_t off = r * 20 + c * 4;
            size_t gsrc = (size_t)(n0 + r) * NKC + k0 + c * 8;
            cpa(smem_u32(base + O_CB + off), g_cosh + gsrc);
            cpa(smem_u32(base + O_SB + off), g_sinh + gsrc);
        }
    };

    auto compute = [&](int buf) {
        const uint32_t* xe = dsu + buf * S_BUF + O_XE;
        const uint32_t* xo = dsu + buf * S_BUF + O_XO;
        const uint32_t* cb = dsu + buf * S_BUF + O_CB;
        const uint32_t* sb = dsu + buf * S_BUF + O_SB;
        #pragma unroll
        for (int j = 0; j < 2; j++) {
            const int kq = j * 8 + tg;
            uint32_t aE[2][4], aO[2][4];
            #pragma unroll
            for (int mi = 0; mi < 2; mi++) {
                int r = m_base + mi * 16 + gr;
                aE[mi][0] = xe[r * 20 + kq];
                aE[mi][1] = xe[(r + 8) * 20 + kq];
                aE[mi][2] = xe[r * 20 + kq + 4];
                aE[mi][3] = xe[(r + 8) * 20 + kq + 4];
                aO[mi][0] = xo[r * 20 + kq];
                aO[mi][1] = xo[(r + 8) * 20 + kq];
                aO[mi][2] = xo[r * 20 + kq + 4];
                aO[mi][3] = xo[(r + 8) * 20 + kq + 4];
            }
            uint32_t bc[4][2], bs[4][2];
            #pragma unroll
            for (int ni = 0; ni < 4; ni++) {
                int n = n_base + ni * 8 + gr;
                bc[ni][0] = cb[n * 20 + kq];
                bc[ni][1] = cb[n * 20 + kq + 4];
                bs[ni][0] = sb[n * 20 + kq];
                bs[ni][1] = sb[n * 20 + kq + 4];
            }
            #pragma unroll
            for (int mi = 0; mi < 2; mi++)
                #pragma unroll
                for (int ni = 0; ni < 4; ni++) {
                    mma16(dP[mi][ni], aE[mi], bc[ni]);
                    mma16(dQ[mi][ni], aO[mi], bs[ni]);
                }
        }
    };

    load(0, 0); CP_COMMIT;
    load(1, 1); CP_COMMIT;
    #pragma unroll 1
    for (int ch = 0; ch < 16; ch++) {
        CP_WAIT1;
        __syncthreads();
        compute(ch % 3);
        if (ch + 2 < 16) { load(ch + 2, (ch + 2) % 3); CP_COMMIT; }
    }
    __syncthreads();

    // epilogue: P += (-1)^n x512; transpose both tiles through smem; write PT/QT
    __half* trs = (__half*)dsu;
    // --- P ---
    #pragma unroll
    for (int mi = 0; mi < 2; mi++) {
        int r0 = row0 + m_base + mi * 16 + gr;
        float xa = g_x512[r0];
        float xb = g_x512[r0 + 8];
        int rl = m_base + mi * 16 + gr;
        #pragma unroll
        for (int ni = 0; ni < 4; ni++) {
            int cl = n_base + ni * 8 + 2 * tg;
            trs[cl * TSTR + rl]           = __float2half_rn(dP[mi][ni][0] + xa);
            trs[(cl + 1) * TSTR + rl]     = __float2half_rn(dP[mi][ni][1] - xa);
            trs[cl * TSTR + rl + 8]       = __float2half_rn(dP[mi][ni][2] + xb);
            trs[(cl + 1) * TSTR + rl + 8] = __float2half_rn(dP[mi][ni][3] - xb);
        }
    }
    __syncthreads();
    #pragma unroll
    for (int pass = 0; pass < 4; pass++) {
        int idx = tid + pass * 256;
        int c = idx >> 4, s = idx & 15;
        uint4 v = *(uint4*)((uint32_t*)trs + c * (TSTR / 2) + s * 4);
        *(uint4*)(g_PT + (size_t)(n0 + c) * NROWS + row0 + s * 8) = v;
    }
    __syncthreads();
    // --- Q ---
    #pragma unroll
    for (int mi = 0; mi < 2; mi++) {
        int rl = m_base + mi * 16 + gr;
        #pragma unroll
        for (int ni = 0; ni < 4; ni++) {
            int cl = n_base + ni * 8 + 2 * tg;
            trs[cl * TSTR + rl]           = __float2half_rn(dQ[mi][ni][0]);
            trs[(cl + 1) * TSTR + rl]     = __float2half_rn(dQ[mi][ni][1]);
            trs[cl * TSTR + rl + 8]       = __float2half_rn(dQ[mi][ni][2]);
            trs[(cl + 1) * TSTR + rl + 8] = __float2half_rn(dQ[mi][ni][3]);
        }
    }
    __syncthreads();
    #pragma unroll
    for (int pass = 0; pass < 4; pass++) {
        int idx = tid + pass * 256;
        int c = idx >> 4, s = idx & 15;
        uint4 v = *(uint4*)((uint32_t*)trs + c * (TSTR / 2) + s * 4);
        *(uint4*)(g_QT + (size_t)(n0 + c) * NROWS + row0 + s * 8) = v;
    }
}

// ---------------- fold P^T/Q^T over seq axis ----------------
// PeT[k][b*512+i] = PT[k][b*1024+i] + PT[k][b*1024+1024-i]  (i=0: just PT)
__global__ void foldPQ() {
    int gid = blockIdx.x * blockDim.x + threadIdx.x;   // 512 * 512 groups of 4
    int k = gid >> 9;
    int cg = (gid & 511) * 4;       // col within [b*512+i] space... 2048 wide
    // process 4 batches' same i-range? No: col space is 2048 = 4*512. Use:
    // gid covers k in 0..511, cg in 0..2047 step 4 -> need 512*512 groups
    int col = cg;                    // 0..2044, but only 512*512 gids -> col < 2048
    int b = col >> 9;
    int i = col & 511;
    const __half* ptr = g_PT + (size_t)k * NROWS + b * 1024;
    const __half* qtr = g_QT + (size_t)k * NROWS + b * 1024;
    __half pe[4], qo[4];
    #pragma unroll
    for (int j = 0; j < 4; j++) {
        int ii = i + j;
        if (ii == 0) {
            pe[0] = ptr[0];
            qo[0] = __float2half_rn(0.f);
        } else {
            pe[j] = __float2half_rn(__half2float(ptr[ii]) + __half2float(ptr[1024 - ii]));
            qo[j] = __float2half_rn(__half2float(qtr[ii]) - __half2float(qtr[1024 - ii]));
        }
    }
    size_t dst = (size_t)k * (BATCH * 512) + col;
    *(half2*)(g_PeT + dst)     = __halves2half2(pe[0], pe[1]);
    *(half2*)(g_PeT + dst + 2) = __halves2half2(pe[2], pe[3]);
    *(half2*)(g_QoT + dst)     = __halves2half2(qo[0], qo[1]);
    *(half2*)(g_QoT + dst + 2) = __halves2half2(qo[2], qo[3]);
}

// ---------------- row 512: out[b,512,k] = sum_i (-1)^i PeT[k][b*512+i] + PT[k][b*1024+512] ----
__global__ void gemv512(float* __restrict__ out) {
    const int wid = threadIdx.x >> 5, lid = threadIdx.x & 31;
    const int k = blockIdx.x * 8 + wid;
    const int b = blockIdx.y;
    const __half* row = g_PeT + (size_t)k * (BATCH * 512) + b * 512;
    float acc = 0.f;
    #pragma unroll 4
    for (int t = 0; t < 16; t++) acc += __half2float(row[lid + t * 32]);
    float sgn = (lid & 1) ? -1.f : 1.f;
    acc *= sgn;
    #pragma unroll
    for (int o = 16; o; o >>= 1) acc += __shfl_xor_sync(0xFFFFFFFFu, acc, o);
    if (lid == 0) {
        float v = acc + __half2float(g_PT[(size_t)k * NROWS + b * 1024 + 512]);
        float* orow = out + ((size_t)b * SEQ + 512) * HID;
        orow[k] = v;
        if (k != 0) orow[HID - k] = v;
    }
}

// ---------------- stage 2: A = C@Pe + corr, B = S@Qo; 4-quadrant scatter ----------------
#define O_PB  5120
#define O_QB  6400

__global__ __launch_bounds__(256)
void stage2(float* __restrict__ out) {
    extern __shared__ uint32_t dsu[];

    const int tid = threadIdx.x;
    const int lane = tid & 31, wid = tid >> 5;
    const int gr = lane >> 2, tg = lane & 3;
    const int m_base = (wid & 3) * 32, n_base = (wid >> 2) * 32;
    const int k0   = blockIdx.x * 64;
    const int row0 = blockIdx.y * 128;
    const int b    = blockIdx.z;

    float dA[2][4][4] = {};
    float dB[2][4][4] = {};

    auto load = [&](int ch, int buf) {
        const int i0 = ch * 32;
        uint32_t* base = dsu + buf * S_BUF;
        #pragma unroll
        for (int i = 0; i < 2; i++) {
            int t = tid + i * 256;
            int r = t >> 2, c = t & 3;
            uint32_t off = r * 20 + c * 4;
            size_t gsrc = (size_t)(row0 + r) * NKC + i0 + c * 8;
            cpa(smem_u32(base + O_XE + off), g_cosh + gsrc);   // reuse O_XE/O_XO slots
            cpa(smem_u32(base + O_XO + off), g_sinh + gsrc);
        }
        {
            int r = tid >> 2, c = tid & 3;
            uint32_t off = r * 20 + c * 4;
            size_t gsrc = (size_t)(k0 + r) * (BATCH * 512) + b * 512 + i0 + c * 8;
            cpa(smem_u32(base + O_PB + off), g_PeT + gsrc);
            cpa(smem_u32(base + O_QB + off), g_QoT + gsrc);
        }
    };

    auto compute = [&](int buf) {
        const uint32_t* cb = dsu + buf * S_BUF + O_XE;
        const uint32_t* sb = dsu + buf * S_BUF + O_XO;
        const uint32_t* pb = dsu + buf * S_BUF + O_PB;
        const uint32_t* qb = dsu + buf * S_BUF + O_QB;
        #pragma unroll
        for (int j = 0; j < 2; j++) {
            const int kq = j * 8 + tg;
            uint32_t aC[2][4], aS[2][4];
            #pragma unroll
            for (int mi = 0; mi < 2; mi++) {
                int r = m_base + mi * 16 + gr;
                aC[mi][0] = cb[r * 20 + kq];
                aC[mi][1] = cb[(r + 8) * 20 + kq];
                aC[mi][2] = cb[r * 20 + kq + 4];
                aC[mi][3] = cb[(r + 8) * 20 + kq + 4];
                aS[mi][0] = sb[r * 20 + kq];
                aS[mi][1] = sb[(r + 8) * 20 + kq];
                aS[mi][2] = sb[r * 20 + kq + 4];
                aS[mi][3] = sb[(r + 8) * 20 + kq + 4];
            }
            uint32_t bP[4][2], bQ[4][2];
            #pragma unroll
            for (int ni = 0; ni < 4; ni++) {
                int n = n_base + ni * 8 + gr;
                bP[ni][0] = pb[n * 20 + kq];
                bP[ni][1] = pb[n * 20 + kq + 4];
                bQ[ni][0] = qb[n * 20 + kq];
                bQ[ni][1] = qb[n * 20 + kq + 4];
            }
            #pragma unroll
            for (int mi = 0; mi < 2; mi++)
                #pragma unroll
                for (int ni = 0; ni < 4; ni++) {
                    mma16(dA[mi][ni], aC[mi], bP[ni]);
                    mma16(dB[mi][ni], aS[mi], bQ[ni]);
                }
        }
    };

    load(0, 0); CP_COMMIT;
    load(1, 1); CP_COMMIT;
    #pragma unroll 1
    for (int ch = 0; ch < 16; ch++) {
        CP_WAIT1;
        __syncthreads();
        compute(ch % 3);
        if (ch + 2 < 16) { load(ch + 2, (ch + 2) % 3); CP_COMMIT; }
    }

    __syncthreads();
    float* sc = (float*)dsu;
    if (tid < 64)
        sc[tid] = __half2float(g_PT[(size_t)(k0 + tid) * NROWS + b * 1024 + 512]);
    __syncthreads();

    const float sgn = (gr & 1) ? -1.f : 1.f;
    float* outb = out + (size_t)b * SEQ * HID;
    #pragma unroll
    for (int mi = 0; mi < 2; mi++) {
        #pragma unroll
        for (int ni = 0; ni < 4; ni++) {
            int lc = n_base + ni * 8 + 2 * tg;
            int col = k0 + lc;
            float c0corr = sgn * sc[lc];
            float c1corr = sgn * sc[lc + 1];
            #pragma unroll
            for (int h = 0; h < 2; h++) {
                int n = row0 + m_base + mi * 16 + gr + h * 8;
                float A0 = dA[mi][ni][h * 2]     + c0corr;
                float A1 = dA[mi][ni][h * 2 + 1] + c1corr;
                float B0 = dB[mi][ni][h * 2];
                float B1 = dB[mi][ni][h * 2 + 1];
                float d0 = A0 - B0, d1 = A1 - B1;
                float s0 = A0 + B0, s1 = A1 + B1;
                float* orow = outb + (size_t)n * HID;
                *(float2*)&orow[col] = make_float2(d0, d1);
                if (col != 0) orow[HID - col] = s0;
                orow[HID - col - 1] = s1;
                if (n != 0) {
                    float* mrow = outb + (size_t)(HID - n) * HID;
                    *(float2*)&mrow[col] = make_float2(s0, s1);
                    if (col != 0) mrow[HID - col] = d0;
                    mrow[HID - col - 1] = d1;
                }
            }
        }
    }
}

// ---------------- Nyquist column (k = 512) from fp32 LUT; symmetric in n ----------------
__global__ __launch_bounds__(256)
void nyq2(float* __restrict__ out) {
    __shared__ float lut[1024];
    __shared__ float pv[1024];
    const int b = blockIdx.y;
    for (int t = threadIdx.x; t < 1024; t += 256) {
        lut[t] = g_lutc[t];
        pv[t]  = g_p512[b * 1024 + t];
    }
    __syncthreads();
    const int wid = threadIdx.x >> 5, lid = threadIdx.x & 31;
    const int n = blockIdx.x * 8 + wid;
    if (n <= 512) {
        float acc = 0.f;
        #pragma unroll 8
        for (int t = 0; t < 32; t++) {
            int i = t * 32 + lid;
            acc += lut[(n * i) & 1023] * pv[i];
        }
        #pragma unroll
        for (int o = 16; o; o >>= 1) acc += __shfl_xor_sync(0xFFFFFFFFu, acc, o);
        if (lid == 0) {
            out[((size_t)b * SEQ + n) * HID + 512] = acc;
            if (n >= 1 && n <= 511)
                out[((size_t)b * SEQ + 1024 - n) * HID + 512] = acc;
        }
    }
}

// ---------------- launcher ----------------
extern "C" void kernel_launch(void* const* d_in, const int* in_sizes, int n_in,
                              void* d_out, int out_size) {
    const float* X = (const float*)d_in[0];
    float* out = (float*)d_out;

    cudaFuncSetAttribute(stage1, cudaFuncAttributeMaxDynamicSharedMemorySize, SMEM_BYTES);
    cudaFuncSetAttribute(stage2, cudaFuncAttributeMaxDynamicSharedMemorySize, SMEM_BYTES);

    fill_lut<<<4, 256>>>();
    fill_tables_h<<<1024, 256>>>();
    foldX<<<2048, 256>>>(X);
    stage1<<<dim3(8, 32), 256, SMEM_BYTES>>>();
    foldPQ<<<1024, 256>>>();
    gemv512<<<dim3(64, 4), 256>>>(out);
    stage2<<<dim3(8, 4, 4), 256, SMEM_BYTES>>>(out);
    nyq2<<<dim3(65, 4), 256>>>(out);
}

// round 8
// speedup vs baseline: 10.5612x; 1.0885x over previous
#include <cuda_runtime.h>
#include <cuda_fp16.h>
#include <cstdint>

#define SEQ   1024
#define HID   1024
#define BATCH 4
#define NROWS (BATCH * SEQ)
#define NKC   512

// ---------------- static device scratch ----------------
__device__ float  g_lutc[1024];
__device__ float  g_luts[1024];
__device__ __half g_cosh[NKC * NKC];       // cos quadrant [n<512][k<512], fp16
__device__ __half g_sinh[NKC * NKC];
__device__ __half g_Xe[NROWS * NKC];       // even fold of X (fp16)
__device__ __half g_Xo[NROWS * NKC];       // odd fold
__device__ float  g_x512[NROWS];           // X[r,512] fp32
__device__ __half g_PT[NKC * NROWS];       // P^T: [k][r]
__device__ __half g_QT[NKC * NROWS];       // Q^T
__device__ __half g_PeT[NKC * BATCH * 512];// Pe^T: [k][b*512+i]
__device__ __half g_QoT[NKC * BATCH * 512];
__device__ float  g_p512[NROWS];           // alternating row-sum of X (fp32)

// ---------------- helpers ----------------
__device__ __forceinline__ uint32_t smem_u32(const void* p) {
    return (uint32_t)__cvta_generic_to_shared(p);
}
__device__ __forceinline__ void cpa(uint32_t s, const void* g) {
    asm volatile("cp.async.cg.shared.global [%0], [%1], 16;" :: "r"(s), "l"(g));
}
#define CP_COMMIT asm volatile("cp.async.commit_group;" ::: "memory")
#define CP_WAIT1  asm volatile("cp.async.wait_group 1;" ::: "memory")

__device__ __forceinline__ void mma16(float* d, const uint32_t* a, const uint32_t* b) {
    asm volatile(
        "mma.sync.aligned.m16n8k16.row.col.f32.f16.f16.f32 "
        "{%0,%1,%2,%3}, {%4,%5,%6,%7}, {%8,%9}, {%0,%1,%2,%3};"
        : "+f"(d[0]), "+f"(d[1]), "+f"(d[2]), "+f"(d[3])
        : "r"(a[0]), "r"(a[1]), "r"(a[2]), "r"(a[3]), "r"(b[0]), "r"(b[1]));
}
__device__ __forceinline__ void ldm4(uint32_t* r, uint32_t saddr) {
    asm volatile("ldmatrix.sync.aligned.m8n8.x4.shared.b16 {%0,%1,%2,%3}, [%4];"
        : "=r"(r[0]), "=r"(r[1]), "=r"(r[2]), "=r"(r[3]) : "r"(saddr));
}

// ---------------- table generation ----------------
__global__ void fill_lut() {
    int m = blockIdx.x * blockDim.x + threadIdx.x;
    float s, c;
    sincospif((float)m * (1.0f / 512.0f), &s, &c);
    g_lutc[m] = c;
    g_luts[m] = s;
}
__global__ void fill_tables_h() {
    int idx = blockIdx.x * blockDim.x + threadIdx.x;   // 512*512
    int j = idx >> 9, k = idx & 511;
    int m = (j * k) & 1023;
    g_cosh[idx] = __float2half_rn(g_lutc[m]);
    g_sinh[idx] = __float2half_rn(g_luts[m]);
}

// ---------------- fold X (fp16 out) + fused Nyquist row-sum ----------------
__global__ __launch_bounds__(256)
void foldX(const float* __restrict__ X) {
    __shared__ float s_red[8];
    const int tid = threadIdx.x;
    const int rloc = tid >> 7;
    const int l128 = tid & 127;
    const int r = blockIdx.x * 2 + rloc;
    const int kg = l128 * 4;
    const float* Xrow = X + (size_t)r * HID;

    float4 fx = *(const float4*)(Xrow + kg);
    float fv[4] = { fx.x, fx.y, fx.z, fx.w };
    float e[4], o[4];
    float part = 0.f;
    #pragma unroll
    for (int j = 0; j < 4; j++) {
        int k = kg + j;
        if (k == 0) {
            e[0] = fv[0]; o[0] = 0.f;
            part += fv[0];
        } else {
            float m = Xrow[1024 - k];
            float sum = fv[j] + m, dif = fv[j] - m;
            e[j] = sum;
            o[j] = dif;
            part += (k & 1) ? -sum : sum;
        }
    }
    if (kg == 0) {
        float x5 = Xrow[512];
        g_x512[r] = x5;
        part += x5;
    }
    size_t dst = (size_t)r * NKC + kg;
    *(half2*)(g_Xe + dst)     = __floats2half2_rn(e[0], e[1]);
    *(half2*)(g_Xe + dst + 2) = __floats2half2_rn(e[2], e[3]);
    *(half2*)(g_Xo + dst)     = __floats2half2_rn(o[0], o[1]);
    *(half2*)(g_Xo + dst + 2) = __floats2half2_rn(o[2], o[3]);

    #pragma unroll
    for (int off = 16; off; off >>= 1) part += __shfl_xor_sync(0xFFFFFFFFu, part, off);
    if ((tid & 31) == 0) s_red[tid >> 5] = part;
    __syncthreads();
    if ((tid & 127) == 0) {
        int w0 = rloc * 4;
        g_p512[r] = s_red[w0] + s_red[w0 + 1] + s_red[w0 + 2] + s_red[w0 + 3];
    }
}

// ---------------- stage 1: P^T/Q^T = (Xe@C)^T, (Xo@S)^T ----------------
// CTA 128(M) x 128(N), 8 warps (4M x 2N), warp tile 32x64, BK=32, 16 chunks.
// ldmatrix.x4 fragment loads; 3-stage cp.async pipeline, 1 barrier/chunk.
#define S1_BUF  10240              // u32 per pipeline buffer
#define O1_XE4  0                  // byte offsets within buffer
#define O1_XO4  (2560 * 4)
#define O1_CB4  (5120 * 4)
#define O1_SB4  (7680 * 4)
#define SMEM1_BYTES (3 * S1_BUF * 4)
#define TSTR  136                  // transpose smem stride (halves)

__global__ __launch_bounds__(256)
void stage1() {
    extern __shared__ uint32_t dsu[];

    const int tid = threadIdx.x;
    const int lane = tid & 31, wid = tid >> 5;
    const int gr = lane >> 2, tg = lane & 3;
    const int m_base = (wid & 3) * 32, n_base = (wid >> 2) * 64;
    const int row0 = blockIdx.y * 128;
    const int n0   = blockIdx.x * 128;

    const uint32_t aoff = (uint32_t)((m_base + (lane & 7) + ((lane >> 3) & 1) * 8) * 80
                                     + ((lane >> 4) & 1) * 16);
    const uint32_t boff = (uint32_t)(((lane & 7) + ((lane >> 4) & 1) * 8) * 80
                                     + ((lane >> 3) & 1) * 16);

    float dP[2][8][4] = {};
    float dQ[2][8][4] = {};

    auto load = [&](int ch, int buf) {
        const int k0h = ch * 32;   // halves
        uint32_t* base = dsu + buf * S1_BUF;
        #pragma unroll
        for (int i = 0; i < 2; i++) {
            int t = tid + i * 256;
            int r = t >> 2, c = t & 3;
            uint32_t off = r * 20 + c * 4;
            size_t ga = (size_t)(row0 + r) * NKC + k0h + c * 8;
            size_t gb = (size_t)(n0 + r) * NKC + k0h + c * 8;
            cpa(smem_u32(base + off),                 g_Xe + ga);
            cpa(smem_u32(base + 2560 + off),          g_Xo + ga);
            cpa(smem_u32(base + 5120 + off),          g_cosh + gb);
            cpa(smem_u32(base + 7680 + off),          g_sinh + gb);
        }
    };

    auto compute = [&](int buf) {
        const uint32_t base = smem_u32(dsu + buf * S1_BUF);
        #pragma unroll
        for (int j = 0; j < 2; j++) {
            uint32_t aE[2][4], aO[2][4];
            #pragma unroll
            for (int mi = 0; mi < 2; mi++) {
                ldm4(aE[mi], base + O1_XE4 + aoff + mi * 1280 + j * 32);
                ldm4(aO[mi], base + O1_XO4 + aoff + mi * 1280 + j * 32);
            }
            uint32_t bc[4][4], bs[4][4];
            #pragma unroll
            for (int g = 0; g < 4; g++) {
                uint32_t nb = (uint32_t)((n_base + g * 16) * 80) + j * 32 + boff;
                ldm4(bc[g], base + O1_CB4 + nb);
                ldm4(bs[g], base + O1_SB4 + nb);
            }
            #pragma unroll
            for (int mi = 0; mi < 2; mi++)
                #pragma unroll
                for (int ni = 0; ni < 8; ni++) {
                    mma16(dP[mi][ni], aE[mi], &bc[ni >> 1][(ni & 1) * 2]);
                    mma16(dQ[mi][ni], aO[mi], &bs[ni >> 1][(ni & 1) * 2]);
                }
        }
    };

    load(0, 0); CP_COMMIT;
    load(1, 1); CP_COMMIT;
    #pragma unroll 1
    for (int ch = 0; ch < 16; ch++) {
        CP_WAIT1;
        __syncthreads();
        compute(ch % 3);
        if (ch + 2 < 16) { load(ch + 2, (ch + 2) % 3); CP_COMMIT; }
    }
    __syncthreads();

    // epilogue: P += (-1)^n x512; transpose 128x128 tiles; write PT/QT
    __half* trs = (__half*)dsu;
    // --- P ---
    #pragma unroll
    for (int mi = 0; mi < 2; mi++) {
        int r0 = row0 + m_base + mi * 16 + gr;
        float xa = g_x512[r0];
        float xb = g_x512[r0 + 8];
        int rl = m_base + mi * 16 + gr;
        #pragma unroll
        for (int ni = 0; ni < 8; ni++) {
            int cl = n_base + ni * 8 + 2 * tg;
            trs[cl * TSTR + rl]           = __float2half_rn(dP[mi][ni][0] + xa);
            trs[(cl + 1) * TSTR + rl]     = __float2half_rn(dP[mi][ni][1] - xa);
            trs[cl * TSTR + rl + 8]       = __float2half_rn(dP[mi][ni][2] + xb);
            trs[(cl + 1) * TSTR + rl + 8] = __float2half_rn(dP[mi][ni][3] - xb);
        }
    }
    __syncthreads();
    #pragma unroll
    for (int pass = 0; pass < 8; pass++) {
        int idx = tid + pass * 256;
        int c = idx >> 4, s = idx & 15;
        uint4 v = *(uint4*)((uint32_t*)trs + c * (TSTR / 2) + s * 4);
        *(uint4*)(g_PT + (size_t)(n0 + c) * NROWS + row0 + s * 8) = v;
    }
    __syncthreads();
    // --- Q ---
    #pragma unroll
    for (int mi = 0; mi < 2; mi++) {
        int rl = m_base + mi * 16 + gr;
        #pragma unroll
        for (int ni = 0; ni < 8; ni++) {
            int cl = n_base + ni * 8 + 2 * tg;
            trs[cl * TSTR + rl]           = __float2half_rn(dQ[mi][ni][0]);
            trs[(cl + 1) * TSTR + rl]     = __float2half_rn(dQ[mi][ni][1]);
            trs[cl * TSTR + rl + 8]       = __float2half_rn(dQ[mi][ni][2]);
            trs[(cl + 1) * TSTR + rl + 8] = __float2half_rn(dQ[mi][ni][3]);
        }
    }
    __syncthreads();
    #pragma unroll
    for (int pass = 0; pass < 8; pass++) {
        int idx = tid + pass * 256;
        int c = idx >> 4, s = idx & 15;
        uint4 v = *(uint4*)((uint32_t*)trs + c * (TSTR / 2) + s * 4);
        *(uint4*)(g_QT + (size_t)(n0 + c) * NROWS + row0 + s * 8) = v;
    }
}

// ---------------- fold P^T/Q^T over seq axis ----------------
__global__ void foldPQ() {
    int gid = blockIdx.x * blockDim.x + threadIdx.x;
    int k = gid >> 9;
    int col = (gid & 511) * 4;
    int b = col >> 9;
    int i = col & 511;
    const __half* ptr = g_PT + (size_t)k * NROWS + b * 1024;
    const __half* qtr = g_QT + (size_t)k * NROWS + b * 1024;
    __half pe[4], qo[4];
    #pragma unroll
    for (int j = 0; j < 4; j++) {
        int ii = i + j;
        if (ii == 0) {
            pe[0] = ptr[0];
            qo[0] = __float2half_rn(0.f);
        } else {
            pe[j] = __float2half_rn(__half2float(ptr[ii]) + __half2float(ptr[1024 - ii]));
            qo[j] = __float2half_rn(__half2float(qtr[ii]) - __half2float(qtr[1024 - ii]));
        }
    }
    size_t dst = (size_t)k * (BATCH * 512) + col;
    *(half2*)(g_PeT + dst)     = __halves2half2(pe[0], pe[1]);
    *(half2*)(g_PeT + dst + 2) = __halves2half2(pe[2], pe[3]);
    *(half2*)(g_QoT + dst)     = __halves2half2(qo[0], qo[1]);
    *(half2*)(g_QoT + dst + 2) = __halves2half2(qo[2], qo[3]);
}

// ---------------- row 512 ----------------
__global__ void gemv512(float* __restrict__ out) {
    const int wid = threadIdx.x >> 5, lid = threadIdx.x & 31;
    const int k = blockIdx.x * 8 + wid;
    const int b = blockIdx.y;
    const __half* row = g_PeT + (size_t)k * (BATCH * 512) + b * 512;
    float acc = 0.f;
    #pragma unroll 4
    for (int t = 0; t < 16; t++) acc += __half2float(row[lid + t * 32]);
    float sgn = (lid & 1) ? -1.f : 1.f;
    acc *= sgn;
    #pragma unroll
    for (int o = 16; o; o >>= 1) acc += __shfl_xor_sync(0xFFFFFFFFu, acc, o);
    if (lid == 0) {
        float v = acc + __half2float(g_PT[(size_t)k * NROWS + b * 1024 + 512]);
        float* orow = out + ((size_t)b * SEQ + 512) * HID;
        orow[k] = v;
        if (k != 0) orow[HID - k] = v;
    }
}

// ---------------- stage 2: A = C@Pe + corr, B = S@Qo; 4-quadrant scatter ----------------
// CTA 128(n) x 64(k), 8 warps 4Mx2N, warp 32x32, BK=32, 16 chunks, ldmatrix.
#define S2_BUF  7680
#define O2_CB4  0
#define O2_SB4  (2560 * 4)
#define O2_PB4  (5120 * 4)
#define O2_QB4  (6400 * 4)
#define SMEM2_BYTES (3 * S2_BUF * 4)

__global__ __launch_bounds__(256)
void stage2(float* __restrict__ out) {
    extern __shared__ uint32_t dsu[];

    const int tid = threadIdx.x;
    const int lane = tid & 31, wid = tid >> 5;
    const int gr = lane >> 2, tg = lane & 3;
    const int m_base = (wid & 3) * 32, n_base = (wid >> 2) * 32;
    const int k0   = blockIdx.x * 64;
    const int row0 = blockIdx.y * 128;
    const int b    = blockIdx.z;

    const uint32_t aoff = (uint32_t)((m_base + (lane & 7) + ((lane >> 3) & 1) * 8) * 80
                                     + ((lane >> 4) & 1) * 16);
    const uint32_t boff = (uint32_t)(((lane & 7) + ((lane >> 4) & 1) * 8) * 80
                                     + ((lane >> 3) & 1) * 16);

    float dA[2][4][4] = {};
    float dB[2][4][4] = {};

    auto load = [&](int ch, int buf) {
        const int i0 = ch * 32;
        uint32_t* base = dsu + buf * S2_BUF;
        #pragma unroll
        for (int i = 0; i < 2; i++) {
            int t = tid + i * 256;
            int r = t >> 2, c = t & 3;
            uint32_t off = r * 20 + c * 4;
            size_t gsrc = (size_t)(row0 + r) * NKC + i0 + c * 8;
            cpa(smem_u32(base + off),        g_cosh + gsrc);
            cpa(smem_u32(base + 2560 + off), g_sinh + gsrc);
        }
        {
            int r = tid >> 2, c = tid & 3;
            uint32_t off = r * 20 + c * 4;
            size_t gsrc = (size_t)(k0 + r) * (BATCH * 512) + b * 512 + i0 + c * 8;
            cpa(smem_u32(base + 5120 + off), g_PeT + gsrc);
            cpa(smem_u32(base + 6400 + off), g_QoT + gsrc);
        }
    };

    auto compute = [&](int buf) {
        const uint32_t base = smem_u32(dsu + buf * S2_BUF);
        #pragma unroll
        for (int j = 0; j < 2; j++) {
            uint32_t aC[2][4], aS[2][4];
            #pragma unroll
            for (int mi = 0; mi < 2; mi++) {
                ldm4(aC[mi], base + O2_CB4 + aoff + mi * 1280 + j * 32);
                ldm4(aS[mi], base + O2_SB4 + aoff + mi * 1280 + j * 32);
            }
            uint32_t bP[2][4], bQ[2][4];
            #pragma unroll
            for (int g = 0; g < 2; g++) {
                uint32_t nb = (uint32_t)((n_base + g * 16) * 80) + j * 32 + boff;
                ldm4(bP[g], base + O2_PB4 + nb);
                ldm4(bQ[g], base + O2_QB4 + nb);
            }
            #pragma unroll
            for (int mi = 0; mi < 2; mi++)
                #pragma unroll
                for (int ni = 0; ni < 4; ni++) {
                    mma16(dA[mi][ni], aC[mi], &bP[ni >> 1][(ni & 1) * 2]);
                    mma16(dB[mi][ni], aS[mi], &bQ[ni >> 1][(ni & 1) * 2]);
                }
        }
    };

    load(0, 0); CP_COMMIT;
    load(1, 1); CP_COMMIT;
    #pragma unroll 1
    for (int ch = 0; ch < 16; ch++) {
        CP_WAIT1;
        __syncthreads();
        compute(ch % 3);
        if (ch + 2 < 16) { load(ch + 2, (ch + 2) % 3); CP_COMMIT; }
    }

    __syncthreads();
    float* sc = (float*)dsu;
    if (tid < 64)
        sc[tid] = __half2float(g_PT[(size_t)(k0 + tid) * NROWS + b * 1024 + 512]);
    __syncthreads();

    const float sgn = (gr & 1) ? -1.f : 1.f;
    float* outb = out + (size_t)b * SEQ * HID;
    #pragma unroll
    for (int mi = 0; mi < 2; mi++) {
        #pragma unroll
        for (int ni = 0; ni < 4; ni++) {
            int lc = n_base + ni * 8 + 2 * tg;
            int col = k0 + lc;
            float c0corr = sgn * sc[lc];
            float c1corr = sgn * sc[lc + 1];
            #pragma unroll
            for (int h = 0; h < 2; h++) {
                int n = row0 + m_base + mi * 16 + gr + h * 8;
                float A0 = dA[mi][ni][h * 2]     + c0corr;
                float A1 = dA[mi][ni][h * 2 + 1] + c1corr;
                float B0 = dB[mi][ni][h * 2];
                float B1 = dB[mi][ni][h * 2 + 1];
                float d0 = A0 - B0, d1 = A1 - B1;
                float s0 = A0 + B0, s1 = A1 + B1;
                float* orow = outb + (size_t)n * HID;
                *(float2*)&orow[col] = make_float2(d0, d1);
                if (col != 0) orow[HID - col] = s0;
                orow[HID - col - 1] = s1;
                if (n != 0) {
                    float* mrow = outb + (size_t)(HID - n) * HID;
                    *(float2*)&mrow[col] = make_float2(s0, s1);
                    if (col != 0) mrow[HID - col] = d0;
                    mrow[HID - col - 1] = d1;
                }
            }
        }
    }
}

// ---------------- Nyquist column (k = 512) ----------------
__global__ __launch_bounds__(256)
void nyq2(float* __restrict__ out) {
    __shared__ float lut[1024];
    __shared__ float pv[1024];
    const int b = blockIdx.y;
    for (int t = threadIdx.x; t < 1024; t += 256) {
        lut[t] = g_lutc[t];
        pv[t]  = g_p512[b * 1024 + t];
    }
    __syncthreads();
    const int wid = threadIdx.x >> 5, lid = threadIdx.x & 31;
    const int n = blockIdx.x * 8 + wid;
    if (n <= 512) {
        float acc = 0.f;
        #pragma unroll 8
        for (int t = 0; t < 32; t++) {
            int i = t * 32 + lid;
            acc += lut[(n * i) & 1023] * pv[i];
        }
        #pragma unroll
        for (int o = 16; o; o >>= 1) acc += __shfl_xor_sync(0xFFFFFFFFu, acc, o);
        if (lid == 0) {
            out[((size_t)b * SEQ + n) * HID + 512] = acc;
            if (n >= 1 && n <= 511)
                out[((size_t)b * SEQ + 1024 - n) * HID + 512] = acc;
        }
    }
}

// ---------------- launcher ----------------
extern "C" void kernel_launch(void* const* d_in, const int* in_sizes, int n_in,
                              void* d_out, int out_size) {
    const float* X = (const float*)d_in[0];
    float* out = (float*)d_out;

    cudaFuncSetAttribute(stage1, cudaFuncAttributeMaxDynamicSharedMemorySize, SMEM1_BYTES);
    cudaFuncSetAttribute(stage2, cudaFuncAttributeMaxDynamicSharedMemorySize, SMEM2_BYTES);

    fill_lut<<<4, 256>>>();
    fill_tables_h<<<1024, 256>>>();
    foldX<<<2048, 256>>>(X);
    stage1<<<dim3(4, 32), 256, SMEM1_BYTES>>>();
    foldPQ<<<1024, 256>>>();
    gemv512<<<dim3(64, 4), 256>>>(out);
    stage2<<<dim3(8, 4, 4), 256, SMEM2_BYTES>>>(out);
    nyq2<<<dim3(65, 4), 256>>>(out);
}

// round 9
// speedup vs baseline: 11.7340x; 1.1110x over previous
#include <cuda_runtime.h>
#include <cuda_fp16.h>
#include <cstdint>

#define SEQ   1024
#define HID   1024
#define BATCH 4
#define NROWS (BATCH * SEQ)
#define NKC   512
#define MF    (BATCH * 512)        // 2048 folded rows

// ---------------- static device scratch ----------------
__device__ float  g_lutc[1024];
__device__ float  g_luts[1024];
__device__ __half g_cosh[NKC * NKC];     // cos quadrant [n<512][k<512], fp16
__device__ __half g_sinh[NKC * NKC];
__device__ __half g_XeE[MF * NKC];       // double-even fold of X (fp16)
__device__ __half g_XoO[MF * NKC];       // double-odd fold
__device__ float  g_x512e[MF];           // X[i,512]+X[1024-i,512] per folded row
__device__ float  g_Xe512[BATCH * 512];  // hidden-fold of row 512 (fp32)
__device__ float  g_x5b[BATCH];          // X[512,512] per batch
__device__ __half g_PeT[NKC * MF];       // Pe^T: [k][b*512+i]
__device__ __half g_QoT[NKC * MF];
__device__ float  g_P512[BATCH * NKC];   // P[b, row 512, k]
__device__ float  g_p512[NROWS];         // alternating row-sum of X (fp32)

// ---------------- helpers ----------------
__device__ __forceinline__ uint32_t smem_u32(const void* p) {
    return (uint32_t)__cvta_generic_to_shared(p);
}
__device__ __forceinline__ void cpa(uint32_t s, const void* g) {
    asm volatile("cp.async.cg.shared.global [%0], [%1], 16;" :: "r"(s), "l"(g));
}
#define CP_COMMIT asm volatile("cp.async.commit_group;" ::: "memory")
#define CP_WAIT1  asm volatile("cp.async.wait_group 1;" ::: "memory")

__device__ __forceinline__ void mma16(float* d, const uint32_t* a, const uint32_t* b) {
    asm volatile(
        "mma.sync.aligned.m16n8k16.row.col.f32.f16.f16.f32 "
        "{%0,%1,%2,%3}, {%4,%5,%6,%7}, {%8,%9}, {%0,%1,%2,%3};"
        : "+f"(d[0]), "+f"(d[1]), "+f"(d[2]), "+f"(d[3])
        : "r"(a[0]), "r"(a[1]), "r"(a[2]), "r"(a[3]), "r"(b[0]), "r"(b[1]));
}
__device__ __forceinline__ void ldm4(uint32_t* r, uint32_t saddr) {
    asm volatile("ldmatrix.sync.aligned.m8n8.x4.shared.b16 {%0,%1,%2,%3}, [%4];"
        : "=r"(r[0]), "=r"(r[1]), "=r"(r[2]), "=r"(r[3]) : "r"(saddr));
}

// ---------------- table generation ----------------
__global__ void fill_lut() {
    int m = blockIdx.x * blockDim.x + threadIdx.x;
    float s, c;
    sincospif((float)m * (1.0f / 512.0f), &s, &c);
    g_lutc[m] = c;
    g_luts[m] = s;
}
__global__ void fill_tables_h() {
    int idx = blockIdx.x * blockDim.x + threadIdx.x;   // 512*512
    int j = idx >> 9, k = idx & 511;
    int m = (j * k) & 1023;
    g_cosh[idx] = __float2half_rn(g_lutc[m]);
    g_sinh[idx] = __float2half_rn(g_luts[m]);
}

// ---------------- double fold of X + Nyquist row-sums ----------------
// Block (i, b): rows r0 = b*1024+i and r1 = b*1024+1024-i (i=0 -> r1 = row 512).
// XeE[b*512+i][k] = Xe(r0)[k] + Xe(r1)[k]  (i=0: Xe(r0) only)
// XoO[b*512+i][k] = Xo(r0)[k] - Xo(r1)[k]  (i=0: zero)
// p512[r] = sum_k (-1)^k X[r,k] for both rows; Xe512/x5b captured at i=0.
__global__ __launch_bounds__(256)
void foldX2(const float* __restrict__ X) {
    __shared__ float se[512], so[512];
    __shared__ float s_red[8];
    __shared__ float sx5[2];
    const int tid = threadIdx.x;
    const int rloc = tid >> 7;
    const int l128 = tid & 127;
    const int kg = l128 * 4;
    const int i = blockIdx.x;
    const int b = blockIdx.y;
    const int r = rloc ? (i == 0 ? b * 1024 + 512 : b * 1024 + 1024 - i)
                       : (b * 1024 + i);
    const float* Xrow = X + (size_t)r * HID;

    float4 fx = *(const float4*)(Xrow + kg);
    float fv[4] = { fx.x, fx.y, fx.z, fx.w };
    float e[4], o[4];
    float part = 0.f;
    #pragma unroll
    for (int j = 0; j < 4; j++) {
        int k = kg + j;
        if (k == 0) {
            e[0] = fv[0]; o[0] = 0.f;
            part += fv[0];
        } else {
            float m = Xrow[1024 - k];
            float sum = fv[j] + m, dif = fv[j] - m;
            e[j] = sum;
            o[j] = dif;
            part += (k & 1) ? -sum : sum;
        }
    }
    if (kg == 0) {
        float x5 = Xrow[512];
        sx5[rloc] = x5;
        part += x5;
    }
    if (rloc == 1) {
        *(float4*)(se + kg) = make_float4(e[0], e[1], e[2], e[3]);
        *(float4*)(so + kg) = make_float4(o[0], o[1], o[2], o[3]);
    }
    #pragma unroll
    for (int off = 16; off; off >>= 1) part += __shfl_xor_sync(0xFFFFFFFFu, part, off);
    if ((tid & 31) == 0) s_red[tid >> 5] = part;
    __syncthreads();
    if ((tid & 127) == 0) {
        int w0 = rloc * 4;
        g_p512[r] = s_red[w0] + s_red[w0 + 1] + s_red[w0 + 2] + s_red[w0 + 3];
    }
    if (rloc == 0) {
        float eE[4], oO[4];
        if (i == 0) {
            #pragma unroll
            for (int j = 0; j < 4; j++) { eE[j] = e[j]; oO[j] = 0.f; }
        } else {
            #pragma unroll
            for (int j = 0; j < 4; j++) {
                eE[j] = e[j] + se[kg + j];
                oO[j] = o[j] - so[kg + j];
            }
        }
        size_t dst = ((size_t)b * 512 + i) * NKC + kg;
        *(half2*)(g_XeE + dst)     = __floats2half2_rn(eE[0], eE[1]);
        *(half2*)(g_XeE + dst + 2) = __floats2half2_rn(eE[2], eE[3]);
        *(half2*)(g_XoO + dst)     = __floats2half2_rn(oO[0], oO[1]);
        *(half2*)(g_XoO + dst + 2) = __floats2half2_rn(oO[2], oO[3]);
        if (kg == 0)
            g_x512e[b * 512 + i] = (i == 0) ? sx5[0] : sx5[0] + sx5[1];
    } else if (i == 0) {
        // row 512: store its hidden-axis even fold (fp32) for the P512 GEMV
        *(float4*)(g_Xe512 + b * 512 + kg) = make_float4(e[0], e[1], e[2], e[3]);
        if (kg == 0) g_x5b[b] = sx5[1];
    }
}

// ---------------- P512 row: P[b,512,k] = Xe512[b] . C[:,k] + (-1)^k X[512,512] ----------------
__global__ __launch_bounds__(256)
void p512row() {
    __shared__ float lut[1024];
    __shared__ float xr[512];
    const int tid = threadIdx.x;
    const int b = blockIdx.y;
    for (int t = tid; t < 1024; t += 256) lut[t] = g_lutc[t];
    for (int t = tid; t < 512; t += 256)  xr[t] = g_Xe512[b * 512 + t];
    __syncthreads();
    const int wid = tid >> 5, lid = tid & 31;
    const int k = blockIdx.x * 8 + wid;   // 0..511
    float acc = 0.f;
    #pragma unroll 4
    for (int t = 0; t < 16; t++) {
        int kp = t * 32 + lid;
        acc += lut[(k * kp) & 1023] * xr[kp];
    }
    #pragma unroll
    for (int o = 16; o; o >>= 1) acc += __shfl_xor_sync(0xFFFFFFFFu, acc, o);
    if (lid == 0)
        g_P512[b * 512 + k] = acc + ((k & 1) ? -g_x5b[b] : g_x5b[b]);
}

// ---------------- stage 1: PeT/QoT = (XeE@C)^T, (XoO@S)^T ----------------
// M = 2048 folded rows. CTA 64(M) x 128(N), 8 warps (2M x 4N), warp 32x32,
// BK=32, 16 chunks, ldmatrix, 3-stage cp.async pipeline.
#define S1_BUF  7680               // u32 per pipeline buffer
#define O1_XE4  0                  // byte offsets: XeE 64x20u32
#define O1_XO4  (1280 * 4)
#define O1_CB4  (2560 * 4)         // C 128x20u32
#define O1_SB4  (5120 * 4)
#define SMEM1_BYTES (3 * S1_BUF * 4)
#define TSTR1   72                 // transpose smem stride (halves), 64+8

__global__ __launch_bounds__(256)
void stage1() {
    extern __shared__ uint32_t dsu[];

    const int tid = threadIdx.x;
    const int lane = tid & 31, wid = tid >> 5;
    const int gr = lane >> 2, tg = lane & 3;
    const int m_base = (wid & 1) * 32, n_base = (wid >> 1) * 32;
    const int m0 = blockIdx.y * 64;    // folded-row tile
    const int n0 = blockIdx.x * 128;   // output k tile

    const uint32_t aoff = (uint32_t)((m_base + (lane & 7) + ((lane >> 3) & 1) * 8) * 80
                                     + ((lane >> 4) & 1) * 16);
    const uint32_t boff = (uint32_t)(((lane & 7) + ((lane >> 4) & 1) * 8) * 80
                                     + ((lane >> 3) & 1) * 16);

    float dP[2][4][4] = {};
    float dQ[2][4][4] = {};

    auto load = [&](int ch, int buf) {
        const int k0h = ch * 32;
        uint32_t* base = dsu + buf * S1_BUF;
        {
            int r = tid >> 2, c = tid & 3;
            uint32_t off = r * 20 + c * 4;
            size_t ga = (size_t)(m0 + r) * NKC + k0h + c * 8;
            cpa(smem_u32(base + off),        g_XeE + ga);
            cpa(smem_u32(base + 1280 + off), g_XoO + ga);
        }
        #pragma unroll
        for (int i = 0; i < 2; i++) {
            int t = tid + i * 256;
            int r = t >> 2, c = t & 3;
            uint32_t off = r * 20 + c * 4;
            size_t gb = (size_t)(n0 + r) * NKC + k0h + c * 8;
            cpa(smem_u32(base + 2560 + off), g_cosh + gb);
            cpa(smem_u32(base + 5120 + off), g_sinh + gb);
        }
    };

    auto compute = [&](int buf) {
        const uint32_t base = smem_u32(dsu + buf * S1_BUF);
        #pragma unroll
        for (int j = 0; j < 2; j++) {
            uint32_t aE[4], aO[4];
            ldm4(aE, base + O1_XE4 + aoff + j * 32);
            ldm4(aO, base + O1_XO4 + aoff + j * 32);
            uint32_t bc[2][4], bs[2][4];
            #pragma unroll
            for (int g = 0; g < 2; g++) {
                uint32_t nb = (uint32_t)((n_base + g * 16) * 80) + j * 32 + boff;
                ldm4(bc[g], base + O1_CB4 + nb);
                ldm4(bs[g], base + O1_SB4 + nb);
            }
            // A frag covers 16 M-rows per ldm4; two mi groups come from the two
            // 16-row halves of the 32-row warp tile -> need second A pair
            uint32_t aE2[4], aO2[4];
            ldm4(aE2, base + O1_XE4 + aoff + 1280 + j * 32);
            ldm4(aO2, base + O1_XO4 + aoff + 1280 + j * 32);
            #pragma unroll
            for (int ni = 0; ni < 4; ni++) {
                mma16(dP[0][ni], aE,  &bc[ni >> 1][(ni & 1) * 2]);
                mma16(dQ[0][ni], aO,  &bs[ni >> 1][(ni & 1) * 2]);
                mma16(dP[1][ni], aE2, &bc[ni >> 1][(ni & 1) * 2]);
                mma16(dQ[1][ni], aO2, &bs[ni >> 1][(ni & 1) * 2]);
            }
        }
    };

    load(0, 0); CP_COMMIT;
    load(1, 1); CP_COMMIT;
    #pragma unroll 1
    for (int ch = 0; ch < 16; ch++) {
        CP_WAIT1;
        __syncthreads();
        compute(ch % 3);
        if (ch + 2 < 16) { load(ch + 2, (ch + 2) % 3); CP_COMMIT; }
    }
    __syncthreads();

    // epilogue: Pe += (-1)^k x512e; transpose 64x128 tiles; write PeT/QoT
    __half* trs = (__half*)dsu;
    // --- Pe ---
    #pragma unroll
    for (int mi = 0; mi < 2; mi++) {
        int rl = m_base + mi * 16 + gr;
        float xa = g_x512e[m0 + rl];
        float xb = g_x512e[m0 + rl + 8];
        #pragma unroll
        for (int ni = 0; ni < 4; ni++) {
            int cl = n_base + ni * 8 + 2 * tg;
            trs[cl * TSTR1 + rl]           = __float2half_rn(dP[mi][ni][0] + xa);
            trs[(cl + 1) * TSTR1 + rl]     = __float2half_rn(dP[mi][ni][1] - xa);
            trs[cl * TSTR1 + rl + 8]       = __float2half_rn(dP[mi][ni][2] + xb);
            trs[(cl + 1) * TSTR1 + rl + 8] = __float2half_rn(dP[mi][ni][3] - xb);
        }
    }
    __syncthreads();
    #pragma unroll
    for (int pass = 0; pass < 4; pass++) {
        int idx = tid + pass * 256;
        int c = idx >> 3, s = idx & 7;
        uint4 v = *(uint4*)((uint32_t*)trs + c * (TSTR1 / 2) + s * 4);
        *(uint4*)(g_PeT + (size_t)(n0 + c) * MF + m0 + s * 8) = v;
    }
    __syncthreads();
    // --- Qo ---
    #pragma unroll
    for (int mi = 0; mi < 2; mi++) {
        int rl = m_base + mi * 16 + gr;
        #pragma unroll
        for (int ni = 0; ni < 4; ni++) {
            int cl = n_base + ni * 8 + 2 * tg;
            trs[cl * TSTR1 + rl]           = __float2half_rn(dQ[mi][ni][0]);
            trs[(cl + 1) * TSTR1 + rl]     = __float2half_rn(dQ[mi][ni][1]);
            trs[cl * TSTR1 + rl + 8]       = __float2half_rn(dQ[mi][ni][2]);
            trs[(cl + 1) * TSTR1 + rl + 8] = __float2half_rn(dQ[mi][ni][3]);
        }
    }
    __syncthreads();
    #pragma unroll
    for (int pass = 0; pass < 4; pass++) {
        int idx = tid + pass * 256;
        int c = idx >> 3, s = idx & 7;
        uint4 v = *(uint4*)((uint32_t*)trs + c * (TSTR1 / 2) + s * 4);
        *(uint4*)(g_QoT + (size_t)(n0 + c) * MF + m0 + s * 8) = v;
    }
}

// ---------------- row 512: out[b,512,k] = sum_i (-1)^i PeT[k][b*512+i] + P512[b,k] ----
__global__ void gemv512(float* __restrict__ out) {
    const int wid = threadIdx.x >> 5, lid = threadIdx.x & 31;
    const int k = blockIdx.x * 8 + wid;
    const int b = blockIdx.y;
    const __half* row = g_PeT + (size_t)k * MF + b * 512;
    float acc = 0.f;
    #pragma unroll 4
    for (int t = 0; t < 16; t++) acc += __half2float(row[lid + t * 32]);
    float sgn = (lid & 1) ? -1.f : 1.f;
    acc *= sgn;
    #pragma unroll
    for (int o = 16; o; o >>= 1) acc += __shfl_xor_sync(0xFFFFFFFFu, acc, o);
    if (lid == 0) {
        float v = acc + g_P512[b * 512 + k];
        float* orow = out + ((size_t)b * SEQ + 512) * HID;
        orow[k] = v;
        if (k != 0) orow[HID - k] = v;
    }
}

// ---------------- stage 2: A = C@Pe + corr, B = S@Qo; 4-quadrant scatter ----------------
#define S2_BUF  7680
#define O2_CB4  0
#define O2_SB4  (2560 * 4)
#define O2_PB4  (5120 * 4)
#define O2_QB4  (6400 * 4)
#define SMEM2_BYTES (3 * S2_BUF * 4)

__global__ __launch_bounds__(256)
void stage2(float* __restrict__ out) {
    extern __shared__ uint32_t dsu[];

    const int tid = threadIdx.x;
    const int lane = tid & 31, wid = tid >> 5;
    const int gr = lane >> 2, tg = lane & 3;
    const int m_base = (wid & 3) * 32, n_base = (wid >> 2) * 32;
    const int k0   = blockIdx.x * 64;
    const int row0 = blockIdx.y * 128;
    const int b    = blockIdx.z;

    const uint32_t aoff = (uint32_t)((m_base + (lane & 7) + ((lane >> 3) & 1) * 8) * 80
                                     + ((lane >> 4) & 1) * 16);
    const uint32_t boff = (uint32_t)(((lane & 7) + ((lane >> 4) & 1) * 8) * 80
                                     + ((lane >> 3) & 1) * 16);

    float dA[2][4][4] = {};
    float dB[2][4][4] = {};

    auto load = [&](int ch, int buf) {
        const int i0 = ch * 32;
        uint32_t* base = dsu + buf * S2_BUF;
        #pragma unroll
        for (int i = 0; i < 2; i++) {
            int t = tid + i * 256;
            int r = t >> 2, c = t & 3;
            uint32_t off = r * 20 + c * 4;
            size_t gsrc = (size_t)(row0 + r) * NKC + i0 + c * 8;
            cpa(smem_u32(base + off),        g_cosh + gsrc);
            cpa(smem_u32(base + 2560 + off), g_sinh + gsrc);
        }
        {
            int r = tid >> 2, c = tid & 3;
            uint32_t off = r * 20 + c * 4;
            size_t gsrc = (size_t)(k0 + r) * MF + b * 512 + i0 + c * 8;
            cpa(smem_u32(base + 5120 + off), g_PeT + gsrc);
            cpa(smem_u32(base + 6400 + off), g_QoT + gsrc);
        }
    };

    auto compute = [&](int buf) {
        const uint32_t base = smem_u32(dsu + buf * S2_BUF);
        #pragma unroll
        for (int j = 0; j < 2; j++) {
            uint32_t aC[2][4], aS[2][4];
            #pragma unroll
            for (int mi = 0; mi < 2; mi++) {
                ldm4(aC[mi], base + O2_CB4 + aoff + mi * 1280 + j * 32);
                ldm4(aS[mi], base + O2_SB4 + aoff + mi * 1280 + j * 32);
            }
            uint32_t bP[2][4], bQ[2][4];
            #pragma unroll
            for (int g = 0; g < 2; g++) {
                uint32_t nb = (uint32_t)((n_base + g * 16) * 80) + j * 32 + boff;
                ldm4(bP[g], base + O2_PB4 + nb);
                ldm4(bQ[g], base + O2_QB4 + nb);
            }
            #pragma unroll
            for (int mi = 0; mi < 2; mi++)
                #pragma unroll
                for (int ni = 0; ni < 4; ni++) {
                    mma16(dA[mi][ni], aC[mi], &bP[ni >> 1][(ni & 1) * 2]);
                    mma16(dB[mi][ni], aS[mi], &bQ[ni >> 1][(ni & 1) * 2]);
                }
        }
    };

    load(0, 0); CP_COMMIT;
    load(1, 1); CP_COMMIT;
    #pragma unroll 1
    for (int ch = 0; ch < 16; ch++) {
        CP_WAIT1;
        __syncthreads();
        compute(ch % 3);
        if (ch + 2 < 16) { load(ch + 2, (ch + 2) % 3); CP_COMMIT; }
    }

    __syncthreads();
    float* sc = (float*)dsu;
    if (tid < 64) sc[tid] = g_P512[b * 512 + k0 + tid];
    __syncthreads();

    const float sgn = (gr & 1) ? -1.f : 1.f;
    float* outb = out + (size_t)b * SEQ * HID;
    #pragma unroll
    for (int mi = 0; mi < 2; mi++) {
        #pragma unroll
        for (int ni = 0; ni < 4; ni++) {
            int lc = n_base + ni * 8 + 2 * tg;
            int col = k0 + lc;
            float c0corr = sgn * sc[lc];
            float c1corr = sgn * sc[lc + 1];
            #pragma unroll
            for (int h = 0; h < 2; h++) {
                int n = row0 + m_base + mi * 16 + gr + h * 8;
                float A0 = dA[mi][ni][h * 2]     + c0corr;
                float A1 = dA[mi][ni][h * 2 + 1] + c1corr;
                float B0 = dB[mi][ni][h * 2];
                float B1 = dB[mi][ni][h * 2 + 1];
                float d0 = A0 - B0, d1 = A1 - B1;
                float s0 = A0 + B0, s1 = A1 + B1;
                float* orow = outb + (size_t)n * HID;
                *(float2*)&orow[col] = make_float2(d0, d1);
                if (col != 0) orow[HID - col] = s0;
                orow[HID - col - 1] = s1;
                if (n != 0) {
                    float* mrow = outb + (size_t)(HID - n) * HID;
                    *(float2*)&mrow[col] = make_float2(s0, s1);
                    if (col != 0) mrow[HID - col] = d0;
                    mrow[HID - col - 1] = d1;
                }
            }
        }
    }
}

// ---------------- Nyquist column (k = 512) ----------------
__global__ __launch_bounds__(256)
void nyq2(float* __restrict__ out) {
    __shared__ float lut[1024];
    __shared__ float pv[1024];
    const int b = blockIdx.y;
    for (int t = threadIdx.x; t < 1024; t += 256) {
        lut[t] = g_lutc[t];
        pv[t]  = g_p512[b * 1024 + t];
    }
    __syncthreads();
    const int wid = threadIdx.x >> 5, lid = threadIdx.x & 31;
    const int n = blockIdx.x * 8 + wid;
    if (n <= 512) {
        float acc = 0.f;
        #pragma unroll 8
        for (int t = 0; t < 32; t++) {
            int i = t * 32 + lid;
            acc += lut[(n * i) & 1023] * pv[i];
        }
        #pragma unroll
        for (int o = 16; o; o >>= 1) acc += __shfl_xor_sync(0xFFFFFFFFu, acc, o);
        if (lid == 0) {
            out[((size_t)b * SEQ + n) * HID + 512] = acc;
            if (n >= 1 && n <= 511)
                out[((size_t)b * SEQ + 1024 - n) * HID + 512] = acc;
        }
    }
}

// ---------------- launcher ----------------
extern "C" void kernel_launch(void* const* d_in, const int* in_sizes, int n_in,
                              void* d_out, int out_size) {
    const float* X = (const float*)d_in[0];
    float* out = (float*)d_out;

    cudaFuncSetAttribute(stage1, cudaFuncAttributeMaxDynamicSharedMemorySize, SMEM1_BYTES);
    cudaFuncSetAttribute(stage2, cudaFuncAttributeMaxDynamicSharedMemorySize, SMEM2_BYTES);

    fill_lut<<<4, 256>>>();
    fill_tables_h<<<1024, 256>>>();
    foldX2<<<dim3(512, 4), 256>>>(X);
    p512row<<<dim3(64, 4), 256>>>();
    stage1<<<dim3(4, 32), 256, SMEM1_BYTES>>>();
    gemv512<<<dim3(64, 4), 256>>>(out);
    stage2<<<dim3(8, 4, 4), 256, SMEM2_BYTES>>>(out);
    nyq2<<<dim3(65, 4), 256>>>(out);
}

// round 10
// speedup vs baseline: 13.2083x; 1.1257x over previous
#include <cuda_runtime.h>
#include <cuda_fp16.h>
#include <cstdint>

#define SEQ   1024
#define HID   1024
#define BATCH 4
#define NROWS (BATCH * SEQ)
#define NKC   512
#define MF    (BATCH * 512)        // 2048 folded rows
#define MFE   (MF + 64)            // extended with row-512 tile (4 used, 60 zero)

// ---------------- static device scratch ----------------
__device__ float  g_lutc[1024];
__device__ float  g_luts[1024];
__device__ __half g_cosh[NKC * NKC];     // cos quadrant [n<512][k<512], fp16
__device__ __half g_sinh[NKC * NKC];
__device__ __half g_XeE[MFE * NKC];      // double-even fold of X (fp16); rows 2048+b = row-512 fold
__device__ __half g_XoO[MFE * NKC];      // double-odd fold; ext rows stay zero
__device__ float  g_x512e[MFE];          // fold of X[.,512]; ext rows: X[b,512,512]
__device__ __half g_PeT[NKC * MFE];      // Pe^T: [k][b*512+i]; cols 2048+b = P[b,512,k]
__device__ __half g_QoT[NKC * MFE];
__device__ float  g_p512[NROWS];         // alternating row-sum of X (fp32)

// ---------------- helpers ----------------
__device__ __forceinline__ uint32_t smem_u32(const void* p) {
    return (uint32_t)__cvta_generic_to_shared(p);
}
__device__ __forceinline__ void cpa(uint32_t s, const void* g) {
    asm volatile("cp.async.cg.shared.global [%0], [%1], 16;" :: "r"(s), "l"(g));
}
#define CP_COMMIT asm volatile("cp.async.commit_group;" ::: "memory")
#define CP_WAIT1  asm volatile("cp.async.wait_group 1;" ::: "memory")

__device__ __forceinline__ void mma16(float* d, const uint32_t* a, const uint32_t* b) {
    asm volatile(
        "mma.sync.aligned.m16n8k16.row.col.f32.f16.f16.f32 "
        "{%0,%1,%2,%3}, {%4,%5,%6,%7}, {%8,%9}, {%0,%1,%2,%3};"
        : "+f"(d[0]), "+f"(d[1]), "+f"(d[2]), "+f"(d[3])
        : "r"(a[0]), "r"(a[1]), "r"(a[2]), "r"(a[3]), "r"(b[0]), "r"(b[1]));
}
__device__ __forceinline__ void ldm4(uint32_t* r, uint32_t saddr) {
    asm volatile("ldmatrix.sync.aligned.m8n8.x4.shared.b16 {%0,%1,%2,%3}, [%4];"
        : "=r"(r[0]), "=r"(r[1]), "=r"(r[2]), "=r"(r[3]) : "r"(saddr));
}

// ---------------- fused table generation ----------------
__global__ __launch_bounds__(256)
void fill_all() {
    const int bx = blockIdx.x;
    if (bx < 1024) {
        int idx = bx * 256 + threadIdx.x;   // 512*512 table entries
        int j = idx >> 9, k = idx & 511;
        int m = (j * k) & 1023;
        float s, c;
        sincospif((float)m * (1.0f / 512.0f), &s, &c);
        g_cosh[idx] = __float2half_rn(c);
        g_sinh[idx] = __float2half_rn(s);
    } else {
        int m = (bx - 1024) * 256 + threadIdx.x;
        float s, c;
        sincospif((float)m * (1.0f / 512.0f), &s, &c);
        g_lutc[m] = c;
        g_luts[m] = s;
    }
}

// ---------------- double fold of X + Nyquist row-sums + row-512 fold ----------------
__global__ __launch_bounds__(256)
void foldX2(const float* __restrict__ X) {
    __shared__ float se[512], so[512];
    __shared__ float s_red[8];
    __shared__ float sx5[2];
    const int tid = threadIdx.x;
    const int rloc = tid >> 7;
    const int l128 = tid & 127;
    const int kg = l128 * 4;
    const int i = blockIdx.x;
    const int b = blockIdx.y;
    const int r = rloc ? (i == 0 ? b * 1024 + 512 : b * 1024 + 1024 - i)
                       : (b * 1024 + i);
    const float* Xrow = X + (size_t)r * HID;

    float4 fx = *(const float4*)(Xrow + kg);
    float fv[4] = { fx.x, fx.y, fx.z, fx.w };
    float e[4], o[4];
    float part = 0.f;
    #pragma unroll
    for (int j = 0; j < 4; j++) {
        int k = kg + j;
        if (k == 0) {
            e[0] = fv[0]; o[0] = 0.f;
            part += fv[0];
        } else {
            float m = Xrow[1024 - k];
            float sum = fv[j] + m, dif = fv[j] - m;
            e[j] = sum;
            o[j] = dif;
            part += (k & 1) ? -sum : sum;
        }
    }
    if (kg == 0) {
        float x5 = Xrow[512];
        sx5[rloc] = x5;
        part += x5;
    }
    if (rloc == 1 && i != 0) {
        *(float4*)(se + kg) = make_float4(e[0], e[1], e[2], e[3]);
        *(float4*)(so + kg) = make_float4(o[0], o[1], o[2], o[3]);
    }
    #pragma unroll
    for (int off = 16; off; off >>= 1) part += __shfl_xor_sync(0xFFFFFFFFu, part, off);
    if ((tid & 31) == 0) s_red[tid >> 5] = part;
    __syncthreads();
    if ((tid & 127) == 0) {
        int w0 = rloc * 4;
        g_p512[r] = s_red[w0] + s_red[w0 + 1] + s_red[w0 + 2] + s_red[w0 + 3];
    }
    if (rloc == 0) {
        float eE[4], oO[4];
        if (i == 0) {
            #pragma unroll
            for (int j = 0; j < 4; j++) { eE[j] = e[j]; oO[j] = 0.f; }
        } else {
            #pragma unroll
            for (int j = 0; j < 4; j++) {
                eE[j] = e[j] + se[kg + j];
                oO[j] = o[j] - so[kg + j];
            }
        }
        size_t dst = ((size_t)b * 512 + i) * NKC + kg;
        *(half2*)(g_XeE + dst)     = __floats2half2_rn(eE[0], eE[1]);
        *(half2*)(g_XeE + dst + 2) = __floats2half2_rn(eE[2], eE[3]);
        *(half2*)(g_XoO + dst)     = __floats2half2_rn(oO[0], oO[1]);
        *(half2*)(g_XoO + dst + 2) = __floats2half2_rn(oO[2], oO[3]);
        if (kg == 0)
            g_x512e[b * 512 + i] = (i == 0) ? sx5[0] : sx5[0] + sx5[1];
    } else if (i == 0) {
        // row 512: hidden-axis even fold -> extended M row 2048+b (fp16)
        size_t dst = ((size_t)MF + b) * NKC + kg;
        *(half2*)(g_XeE + dst)     = __floats2half2_rn(e[0], e[1]);
        *(half2*)(g_XeE + dst + 2) = __floats2half2_rn(e[2], e[3]);
        if (kg == 0) g_x512e[MF + b] = sx5[1];   // X[b,512,512]
    }
}

// ---------------- stage 1: PeT/QoT = (XeE@C)^T, (XoO@S)^T over 2112 rows ----------------
// CTA 64(M) x 128(N), 8 warps (2M x 4N), warp 32x32, BK=32, 16 chunks,
// ldmatrix, 3-stage cp.async pipeline.
#define S1_BUF  7680
#define O1_XE4  0
#define O1_XO4  (1280 * 4)
#define O1_CB4  (2560 * 4)
#define O1_SB4  (5120 * 4)
#define SMEM1_BYTES (3 * S1_BUF * 4)
#define TSTR1   72

__global__ __launch_bounds__(256)
void stage1() {
    extern __shared__ uint32_t dsu[];

    const int tid = threadIdx.x;
    const int lane = tid & 31, wid = tid >> 5;
    const int gr = lane >> 2, tg = lane & 3;
    const int m_base = (wid & 1) * 32, n_base = (wid >> 1) * 32;
    const int m0 = blockIdx.y * 64;
    const int n0 = blockIdx.x * 128;

    const uint32_t aoff = (uint32_t)((m_base + (lane & 7) + ((lane >> 3) & 1) * 8) * 80
                                     + ((lane >> 4) & 1) * 16);
    const uint32_t boff = (uint32_t)(((lane & 7) + ((lane >> 4) & 1) * 8) * 80
                                     + ((lane >> 3) & 1) * 16);

    float dP[2][4][4] = {};
    float dQ[2][4][4] = {};

    auto load = [&](int ch, int buf) {
        const int k0h = ch * 32;
        uint32_t* base = dsu + buf * S1_BUF;
        {
            int r = tid >> 2, c = tid & 3;
            uint32_t off = r * 20 + c * 4;
            size_t ga = (size_t)(m0 + r) * NKC + k0h + c * 8;
            cpa(smem_u32(base + off),        g_XeE + ga);
            cpa(smem_u32(base + 1280 + off), g_XoO + ga);
        }
        #pragma unroll
        for (int i = 0; i < 2; i++) {
            int t = tid + i * 256;
            int r = t >> 2, c = t & 3;
            uint32_t off = r * 20 + c * 4;
            size_t gb = (size_t)(n0 + r) * NKC + k0h + c * 8;
            cpa(smem_u32(base + 2560 + off), g_cosh + gb);
            cpa(smem_u32(base + 5120 + off), g_sinh + gb);
        }
    };

    auto compute = [&](int buf) {
        const uint32_t base = smem_u32(dsu + buf * S1_BUF);
        #pragma unroll
        for (int j = 0; j < 2; j++) {
            uint32_t aE[4], aO[4], aE2[4], aO2[4];
            ldm4(aE,  base + O1_XE4 + aoff + j * 32);
            ldm4(aO,  base + O1_XO4 + aoff + j * 32);
            ldm4(aE2, base + O1_XE4 + aoff + 1280 + j * 32);
            ldm4(aO2, base + O1_XO4 + aoff + 1280 + j * 32);
            uint32_t bc[2][4], bs[2][4];
            #pragma unroll
            for (int g = 0; g < 2; g++) {
                uint32_t nb = (uint32_t)((n_base + g * 16) * 80) + j * 32 + boff;
                ldm4(bc[g], base + O1_CB4 + nb);
                ldm4(bs[g], base + O1_SB4 + nb);
            }
            #pragma unroll
            for (int ni = 0; ni < 4; ni++) {
                mma16(dP[0][ni], aE,  &bc[ni >> 1][(ni & 1) * 2]);
                mma16(dQ[0][ni], aO,  &bs[ni >> 1][(ni & 1) * 2]);
                mma16(dP[1][ni], aE2, &bc[ni >> 1][(ni & 1) * 2]);
                mma16(dQ[1][ni], aO2, &bs[ni >> 1][(ni & 1) * 2]);
            }
        }
    };

    load(0, 0); CP_COMMIT;
    load(1, 1); CP_COMMIT;
    #pragma unroll 1
    for (int ch = 0; ch < 16; ch++) {
        CP_WAIT1;
        __syncthreads();
        compute(ch % 3);
        if (ch + 2 < 16) { load(ch + 2, (ch + 2) % 3); CP_COMMIT; }
    }
    __syncthreads();

    // epilogue: Pe += (-1)^k x512e; transpose 64x128 tiles; write PeT/QoT
    __half* trs = (__half*)dsu;
    #pragma unroll
    for (int mi = 0; mi < 2; mi++) {
        int rl = m_base + mi * 16 + gr;
        float xa = g_x512e[m0 + rl];
        float xb = g_x512e[m0 + rl + 8];
        #pragma unroll
        for (int ni = 0; ni < 4; ni++) {
            int cl = n_base + ni * 8 + 2 * tg;
            trs[cl * TSTR1 + rl]           = __float2half_rn(dP[mi][ni][0] + xa);
            trs[(cl + 1) * TSTR1 + rl]     = __float2half_rn(dP[mi][ni][1] - xa);
            trs[cl * TSTR1 + rl + 8]       = __float2half_rn(dP[mi][ni][2] + xb);
            trs[(cl + 1) * TSTR1 + rl + 8] = __float2half_rn(dP[mi][ni][3] - xb);
        }
    }
    __syncthreads();
    #pragma unroll
    for (int pass = 0; pass < 4; pass++) {
        int idx = tid + pass * 256;
        int c = idx >> 3, s = idx & 7;
        uint4 v = *(uint4*)((uint32_t*)trs + c * (TSTR1 / 2) + s * 4);
        *(uint4*)(g_PeT + (size_t)(n0 + c) * MFE + m0 + s * 8) = v;
    }
    __syncthreads();
    #pragma unroll
    for (int mi = 0; mi < 2; mi++) {
        int rl = m_base + mi * 16 + gr;
        #pragma unroll
        for (int ni = 0; ni < 4; ni++) {
            int cl = n_base + ni * 8 + 2 * tg;
            trs[cl * TSTR1 + rl]           = __float2half_rn(dQ[mi][ni][0]);
            trs[(cl + 1) * TSTR1 + rl]     = __float2half_rn(dQ[mi][ni][1]);
            trs[cl * TSTR1 + rl + 8]       = __float2half_rn(dQ[mi][ni][2]);
            trs[(cl + 1) * TSTR1 + rl + 8] = __float2half_rn(dQ[mi][ni][3]);
        }
    }
    __syncthreads();
    #pragma unroll
    for (int pass = 0; pass < 4; pass++) {
        int idx = tid + pass * 256;
        int c = idx >> 3, s = idx & 7;
        uint4 v = *(uint4*)((uint32_t*)trs + c * (TSTR1 / 2) + s * 4);
        *(uint4*)(g_QoT + (size_t)(n0 + c) * MFE + m0 + s * 8) = v;
    }
}

// ---------------- fused tail: row 512 GEMV + Nyquist column ----------------
__global__ __launch_bounds__(256)
void tail512(float* __restrict__ out) {
    const int b = blockIdx.y;
    const int wid = threadIdx.x >> 5, lid = threadIdx.x & 31;
    if (blockIdx.x < 64) {
        // out[b,512,k] = sum_i (-1)^i PeT[k][b*512+i] + P512  (P512 from ext col)
        const int k = blockIdx.x * 8 + wid;
        const __half* row = g_PeT + (size_t)k * MFE + b * 512;
        float acc = 0.f;
        #pragma unroll 4
        for (int t = 0; t < 16; t++) acc += __half2float(row[lid + t * 32]);
        float sgn = (lid & 1) ? -1.f : 1.f;
        acc *= sgn;
        #pragma unroll
        for (int o = 16; o; o >>= 1) acc += __shfl_xor_sync(0xFFFFFFFFu, acc, o);
        if (lid == 0) {
            float v = acc + __half2float(g_PeT[(size_t)k * MFE + MF + b]);
            float* orow = out + ((size_t)b * SEQ + 512) * HID;
            orow[k] = v;
            if (k != 0) orow[HID - k] = v;
        }
    } else {
        __shared__ float lut[1024];
        __shared__ float pv[1024];
        for (int t = threadIdx.x; t < 1024; t += 256) {
            lut[t] = g_lutc[t];
            pv[t]  = g_p512[b * 1024 + t];
        }
        __syncthreads();
        const int n = (blockIdx.x - 64) * 8 + wid;
        if (n <= 512) {
            float acc = 0.f;
            #pragma unroll 8
            for (int t = 0; t < 32; t++) {
                int i = t * 32 + lid;
                acc += lut[(n * i) & 1023] * pv[i];
            }
            #pragma unroll
            for (int o = 16; o; o >>= 1) acc += __shfl_xor_sync(0xFFFFFFFFu, acc, o);
            if (lid == 0) {
                out[((size_t)b * SEQ + n) * HID + 512] = acc;
                if (n >= 1 && n <= 511)
                    out[((size_t)b * SEQ + 1024 - n) * HID + 512] = acc;
            }
        }
    }
}

// ---------------- stage 2: A = C@Pe + corr, B = S@Qo; 4-quadrant scatter ----------------
#define S2_BUF  7680
#define O2_CB4  0
#define O2_SB4  (2560 * 4)
#define O2_PB4  (5120 * 4)
#define O2_QB4  (6400 * 4)
#define SMEM2_BYTES (3 * S2_BUF * 4)

__global__ __launch_bounds__(256)
void stage2(float* __restrict__ out) {
    extern __shared__ uint32_t dsu[];

    const int tid = threadIdx.x;
    const int lane = tid & 31, wid = tid >> 5;
    const int gr = lane >> 2, tg = lane & 3;
    const int m_base = (wid & 3) * 32, n_base = (wid >> 2) * 32;
    const int k0   = blockIdx.x * 64;
    const int row0 = blockIdx.y * 128;
    const int b    = blockIdx.z;

    const uint32_t aoff = (uint32_t)((m_base + (lane & 7) + ((lane >> 3) & 1) * 8) * 80
                                     + ((lane >> 4) & 1) * 16);
    const uint32_t boff = (uint32_t)(((lane & 7) + ((lane >> 4) & 1) * 8) * 80
                                     + ((lane >> 3) & 1) * 16);

    float dA[2][4][4] = {};
    float dB[2][4][4] = {};

    auto load = [&](int ch, int buf) {
        const int i0 = ch * 32;
        uint32_t* base = dsu + buf * S2_BUF;
        #pragma unroll
        for (int i = 0; i < 2; i++) {
            int t = tid + i * 256;
            int r = t >> 2, c = t & 3;
            uint32_t off = r * 20 + c * 4;
            size_t gsrc = (size_t)(row0 + r) * NKC + i0 + c * 8;
            cpa(smem_u32(base + off),        g_cosh + gsrc);
            cpa(smem_u32(base + 2560 + off), g_sinh + gsrc);
        }
        {
            int r = tid >> 2, c = tid & 3;
            uint32_t off = r * 20 + c * 4;
            size_t gsrc = (size_t)(k0 + r) * MFE + b * 512 + i0 + c * 8;
            cpa(smem_u32(base + 5120 + off), g_PeT + gsrc);
            cpa(smem_u32(base + 6400 + off), g_QoT + gsrc);
        }
    };

    auto compute = [&](int buf) {
        const uint32_t base = smem_u32(dsu + buf * S2_BUF);
        #pragma unroll
        for (int j = 0; j < 2; j++) {
            uint32_t aC[2][4], aS[2][4];
            #pragma unroll
            for (int mi = 0; mi < 2; mi++) {
                ldm4(aC[mi], base + O2_CB4 + aoff + mi * 1280 + j * 32);
                ldm4(aS[mi], base + O2_SB4 + aoff + mi * 1280 + j * 32);
            }
            uint32_t bP[2][4], bQ[2][4];
            #pragma unroll
            for (int g = 0; g < 2; g++) {
                uint32_t nb = (uint32_t)((n_base + g * 16) * 80) + j * 32 + boff;
                ldm4(bP[g], base + O2_PB4 + nb);
                ldm4(bQ[g], base + O2_QB4 + nb);
            }
            #pragma unroll
            for (int mi = 0; mi < 2; mi++)
                #pragma unroll
                for (int ni = 0; ni < 4; ni++) {
                    mma16(dA[mi][ni], aC[mi], &bP[ni >> 1][(ni & 1) * 2]);
                    mma16(dB[mi][ni], aS[mi], &bQ[ni >> 1][(ni & 1) * 2]);
                }
        }
    };

    load(0, 0); CP_COMMIT;
    load(1, 1); CP_COMMIT;
    #pragma unroll 1
    for (int ch = 0; ch < 16; ch++) {
        CP_WAIT1;
        __syncthreads();
        compute(ch % 3);
        if (ch + 2 < 16) { load(ch + 2, (ch + 2) % 3); CP_COMMIT; }
    }

    __syncthreads();
    float* sc = (float*)dsu;
    if (tid < 64)
        sc[tid] = __half2float(g_PeT[(size_t)(k0 + tid) * MFE + MF + b]);
    __syncthreads();

    const float sgn = (gr & 1) ? -1.f : 1.f;
    float* outb = out + (size_t)b * SEQ * HID;
    #pragma unroll
    for (int mi = 0; mi < 2; mi++) {
        #pragma unroll
        for (int ni = 0; ni < 4; ni++) {
            int lc = n_base + ni * 8 + 2 * tg;
            int col = k0 + lc;
            float c0corr = sgn * sc[lc];
            float c1corr = sgn * sc[lc + 1];
            #pragma unroll
            for (int h = 0; h < 2; h++) {
                int n = row0 + m_base + mi * 16 + gr + h * 8;
                float A0 = dA[mi][ni][h * 2]     + c0corr;
                float A1 = dA[mi][ni][h * 2 + 1] + c1corr;
                float B0 = dB[mi][ni][h * 2];
                float B1 = dB[mi][ni][h * 2 + 1];
                float d0 = A0 - B0, d1 = A1 - B1;
                float s0 = A0 + B0, s1 = A1 + B1;
                float* orow = outb + (size_t)n * HID;
                *(float2*)&orow[col] = make_float2(d0, d1);
                if (col != 0) orow[HID - col] = s0;
                orow[HID - col - 1] = s1;
                if (n != 0) {
                    float* mrow = outb + (size_t)(HID - n) * HID;
                    *(float2*)&mrow[col] = make_float2(s0, s1);
                    if (col != 0) mrow[HID - col] = d0;
                    mrow[HID - col - 1] = d1;
                }
            }
        }
    }
}

// ---------------- launcher ----------------
extern "C" void kernel_launch(void* const* d_in, const int* in_sizes, int n_in,
                              void* d_out, int out_size) {
    const float* X = (const float*)d_in[0];
    float* out = (float*)d_out;

    cudaFuncSetAttribute(stage1, cudaFuncAttributeMaxDynamicSharedMemorySize, SMEM1_BYTES);
    cudaFuncSetAttribute(stage2, cudaFuncAttributeMaxDynamicSharedMemorySize, SMEM2_BYTES);

    fill_all<<<1028, 256>>>();
    foldX2<<<dim3(512, 4), 256>>>(X);
    stage1<<<dim3(4, 33), 256, SMEM1_BYTES>>>();
    tail512<<<dim3(129, 4), 256>>>(out);
    stage2<<<dim3(8, 4, 4), 256, SMEM2_BYTES>>>(out);
}